// round 2
// baseline (speedup 1.0000x reference)
#include <cuda_runtime.h>
#include <math.h>

#define BDIM   4
#define NTOK   1024
#define CDIM   768
#define NH     12
#define HD     64
#define BH     (BDIM*NH)        // 48
#define MROWS  (BDIM*NTOK)      // 4096
#define THREEC (3*CDIM)         // 2304

#define QROWS  32               // q-rows per fused block
#define NCHUNK (BH*(NTOK/QROWS)) // 1536 partial-stat chunks
#define SPAD   1032             // scores row pitch (floats)

// -------- scratch (static device memory; no allocs allowed) --------
__device__ float g_q[BH*NTOK*HD];                 // [BH, N, hd]
__device__ float g_k[BH*NTOK*HD];
__device__ float g_v[BH*NTOK*HD];
__device__ float g_attn[(size_t)BH*NTOK*NTOK];    // 201 MB: softmax probs
__device__ float g_ps[NCHUNK*NTOK];               // partial col sum(p)
__device__ float g_pp[NCHUNK*NTOK];               // partial col sum(p*logp)
__device__ float g_mask[NTOK];
__device__ float g_ctx[MROWS*CDIM];               // (attn*mask)@v in [B,N,C]

// ============================================================
// K1: qkv = x @ qkv_w.T ; scatter into g_q/g_k/g_v [BH,N,hd]
// ============================================================
__global__ void qkv_gemm(const float* __restrict__ x, const float* __restrict__ w) {
    __shared__ float As[16][65];
    __shared__ float Bs[16][65];
    const int m0 = blockIdx.y * 64;
    const int n0 = blockIdx.x * 64;
    const int tid = threadIdx.x;
    const int tx = tid & 15, ty = tid >> 4;
    float acc[4][4] = {};

    for (int k0 = 0; k0 < CDIM; k0 += 16) {
        for (int idx = tid; idx < 64 * 16; idx += 256) {
            int r = idx >> 4, c = idx & 15;
            As[c][r] = x[(m0 + r) * CDIM + k0 + c];
            Bs[c][r] = w[(n0 + r) * CDIM + k0 + c];
        }
        __syncthreads();
        #pragma unroll
        for (int kk = 0; kk < 16; kk++) {
            float a[4], b[4];
            #pragma unroll
            for (int i = 0; i < 4; i++) a[i] = As[kk][ty + 16 * i];
            #pragma unroll
            for (int j = 0; j < 4; j++) b[j] = Bs[kk][tx + 16 * j];
            #pragma unroll
            for (int i = 0; i < 4; i++)
                #pragma unroll
                for (int j = 0; j < 4; j++) acc[i][j] += a[i] * b[j];
        }
        __syncthreads();
    }
    const int b = m0 / NTOK;
    const int three = n0 / CDIM;
    const int h = (n0 % CDIM) / HD;
    float* dst = (three == 0) ? g_q : (three == 1) ? g_k : g_v;
    const int base = ((b * NH + h) * NTOK) * HD;
    #pragma unroll
    for (int i = 0; i < 4; i++) {
        int tok = (m0 % NTOK) + ty + 16 * i;
        #pragma unroll
        for (int j = 0; j < 4; j++) {
            int d = tx + 16 * j;
            dst[base + tok * HD + d] = acc[i][j];
        }
    }
}

// ============================================================
// K2 (FUSED): scores -> row softmax -> p + column stats
// Block: 256 threads, 32 q-rows of one (b,h); scores row band in smem.
// ============================================================
__global__ void qk_softmax_stats() {
    extern __shared__ float sm[];
    float* S   = sm;                        // [32][SPAD]
    float* Kt  = S  + QROWS * SPAD;         // [64][68]   Kt[d][col]
    float* Qt  = Kt + 64 * 68;              // [64][36]   Qt[d][row]

    const int bh = blockIdx.y;
    const int q0 = blockIdx.x * QROWS;
    const int tid = threadIdx.x;
    const int tx = tid & 15, ty = tid >> 4;
    const float* qb = g_q + (bh * NTOK + q0) * HD;
    const float* kb = g_k + bh * NTOK * HD;

    // stage Q (transposed): Qt[d][r]
    for (int idx = tid; idx < QROWS * HD; idx += 256) {
        int r = idx >> 6, d = idx & 63;
        Qt[d * 36 + r] = qb[r * HD + d];
    }

    const float scale = 0.125f;  // hd^-0.5

    // ---- scores: loop over 64-wide K tiles, 2x4 microtile ----
    for (int k0 = 0; k0 < NTOK; k0 += 64) {
        __syncthreads();  // protect Kt from prior readers (also covers Qt init)
        for (int idx = tid; idx < 64 * 64; idx += 256) {
            int c = idx >> 6, d = idx & 63;
            Kt[d * 68 + c] = kb[(k0 + c) * HD + d];
        }
        __syncthreads();

        float acc[2][4] = {};
        #pragma unroll
        for (int d = 0; d < 64; d++) {
            const float4 kv = *(const float4*)(Kt + d * 68 + tx * 4);
            float qa = Qt[d * 36 + ty];
            float qc = Qt[d * 36 + ty + 16];
            acc[0][0] += qa * kv.x; acc[0][1] += qa * kv.y;
            acc[0][2] += qa * kv.z; acc[0][3] += qa * kv.w;
            acc[1][0] += qc * kv.x; acc[1][1] += qc * kv.y;
            acc[1][2] += qc * kv.z; acc[1][3] += qc * kv.w;
        }
        #pragma unroll
        for (int i = 0; i < 2; i++) {
            float* row = S + (ty + 16 * i) * SPAD + k0 + tx * 4;
            row[0] = acc[i][0] * scale; row[1] = acc[i][1] * scale;
            row[2] = acc[i][2] * scale; row[3] = acc[i][3] * scale;
        }
    }
    __syncthreads();

    // ---- row softmax: warp w owns rows 4w..4w+3; store logp in S ----
    const int wid = tid >> 5, lane = tid & 31;
    #pragma unroll
    for (int rr = 0; rr < 4; rr++) {
        float* row = S + (wid * 4 + rr) * SPAD;
        float m = -1e30f;
        #pragma unroll 8
        for (int i = 0; i < 32; i++) m = fmaxf(m, row[lane + 32 * i]);
        #pragma unroll
        for (int o = 16; o > 0; o >>= 1) m = fmaxf(m, __shfl_xor_sync(~0u, m, o));
        float s = 0.f;
        #pragma unroll 8
        for (int i = 0; i < 32; i++) s += __expf(row[lane + 32 * i] - m);
        #pragma unroll
        for (int o = 16; o > 0; o >>= 1) s += __shfl_xor_sync(~0u, s, o);
        float l = m + __logf(s);
        #pragma unroll 8
        for (int i = 0; i < 32; i++) row[lane + 32 * i] -= l;
    }
    __syncthreads();

    // ---- column pass: p = exp(logp); write p + per-block column stats ----
    float ssum[4] = {0.f, 0.f, 0.f, 0.f};
    float psum[4] = {0.f, 0.f, 0.f, 0.f};
    const size_t arow = (size_t)(bh * NTOK + q0) * NTOK;
    for (int r = 0; r < QROWS; r++) {
        const float* srow = S + r * SPAD;
        float* grow = g_attn + arow + (size_t)r * NTOK;
        #pragma unroll
        for (int k = 0; k < 4; k++) {
            int col = tid + 256 * k;
            float lp = srow[col];
            float p = __expf(lp);
            ssum[k] += p;
            psum[k] += p * lp;
            grow[col] = p;
        }
    }
    const int chunk = bh * (NTOK / QROWS) + blockIdx.x;
    #pragma unroll
    for (int k = 0; k < 4; k++) {
        g_ps[chunk * NTOK + tid + 256 * k] = ssum[k];
        g_pp[chunk * NTOK + tid + 256 * k] = psum[k];
    }
}

// ============================================================
// K3: merge column partials -> entropies -> mask
// ============================================================
__global__ void finalize_mask(const int* __restrict__ cur_epoch_ptr) {
    const int j = blockIdx.x * 256 + threadIdx.x;   // 0..1023
    float s0 = 0.f, s1 = 0.f, p0 = 0.f, p1 = 0.f;
    #pragma unroll 4
    for (int c = 0; c < NCHUNK; c += 2) {
        s0 += g_ps[c * NTOK + j];
        s1 += g_ps[(c + 1) * NTOK + j];
        p0 += g_pp[c * NTOK + j];
        p1 += g_pp[(c + 1) * NTOK + j];
    }
    float s = s0 + s1, pp = p0 + p1;
    const int ce = *cur_epoch_ptr;
    float factor = 0.f;
    for (int i = 0; i < ce; i++) factor += expf(-(float)(i + 1));
    factor *= 5.0f;
    const float thr = logf((float)CDIM) - factor;
    const float ent = logf(s) - pp / s;
    g_mask[j] = (ent <= thr) ? 1.0f : 0.0f;
}

// ============================================================
// K4: ctx[b,q,h,d] = sum_k attn[bh,q,k]*mask[k]*v[bh,k,d]
// ============================================================
__global__ void av_gemm() {
    __shared__ float Ps[64][17];
    __shared__ float Vs[16][65];
    const int bh = blockIdx.y;
    const int q0 = blockIdx.x * 64;
    const int tid = threadIdx.x;
    const int tx = tid & 15, ty = tid >> 4;
    const float* vb = g_v + bh * NTOK * HD;
    const float* pb = g_attn + (size_t)(bh * NTOK + q0) * NTOK;
    float acc[4][4] = {};

    for (int k0 = 0; k0 < NTOK; k0 += 16) {
        for (int idx = tid; idx < 64 * 16; idx += 256) {
            int r = idx >> 4, c = idx & 15;
            Ps[r][c] = pb[(size_t)r * NTOK + k0 + c] * g_mask[k0 + c];
        }
        for (int idx = tid; idx < 16 * 64; idx += 256) {
            int r = idx >> 6, c = idx & 63;
            Vs[r][c] = vb[(k0 + r) * HD + c];
        }
        __syncthreads();
        #pragma unroll
        for (int kk = 0; kk < 16; kk++) {
            float a[4], b[4];
            #pragma unroll
            for (int i = 0; i < 4; i++) a[i] = Ps[ty + 16 * i][kk];
            #pragma unroll
            for (int j = 0; j < 4; j++) b[j] = Vs[kk][tx + 16 * j];
            #pragma unroll
            for (int i = 0; i < 4; i++)
                #pragma unroll
                for (int j = 0; j < 4; j++) acc[i][j] += a[i] * b[j];
        }
        __syncthreads();
    }
    const int b = bh / NH, h = bh % NH;
    #pragma unroll
    for (int i = 0; i < 4; i++) {
        int q = q0 + ty + 16 * i;
        #pragma unroll
        for (int j = 0; j < 4; j++) {
            int d = tx + 16 * j;
            g_ctx[(b * NTOK + q) * CDIM + h * HD + d] = acc[i][j];
        }
    }
}

// ============================================================
// K5: out = ctx @ proj_w.T + proj_b
// ============================================================
__global__ void proj_gemm(const float* __restrict__ w, const float* __restrict__ bias,
                          float* __restrict__ out) {
    __shared__ float As[16][65];
    __shared__ float Bs[16][65];
    const int m0 = blockIdx.y * 64;
    const int n0 = blockIdx.x * 64;
    const int tid = threadIdx.x;
    const int tx = tid & 15, ty = tid >> 4;
    float acc[4][4] = {};

    for (int k0 = 0; k0 < CDIM; k0 += 16) {
        for (int idx = tid; idx < 64 * 16; idx += 256) {
            int r = idx >> 4, c = idx & 15;
            As[c][r] = g_ctx[(m0 + r) * CDIM + k0 + c];
            Bs[c][r] = w[(n0 + r) * CDIM + k0 + c];
        }
        __syncthreads();
        #pragma unroll
        for (int kk = 0; kk < 16; kk++) {
            float a[4], b[4];
            #pragma unroll
            for (int i = 0; i < 4; i++) a[i] = As[kk][ty + 16 * i];
            #pragma unroll
            for (int j = 0; j < 4; j++) b[j] = Bs[kk][tx + 16 * j];
            #pragma unroll
            for (int i = 0; i < 4; i++)
                #pragma unroll
                for (int j = 0; j < 4; j++) acc[i][j] += a[i] * b[j];
        }
        __syncthreads();
    }
    #pragma unroll
    for (int i = 0; i < 4; i++) {
        int m = m0 + ty + 16 * i;
        #pragma unroll
        for (int j = 0; j < 4; j++) {
            int n = n0 + tx + 16 * j;
            out[m * CDIM + n] = acc[i][j] + bias[n];
        }
    }
}

// ============================================================
extern "C" void kernel_launch(void* const* d_in, const int* in_sizes, int n_in,
                              void* d_out, int out_size) {
    const float* x      = (const float*)d_in[0];
    const float* qkv_w  = (const float*)d_in[1];
    const float* proj_w = (const float*)d_in[2];
    const float* proj_b = (const float*)d_in[3];
    const int*   ce     = (const int*)d_in[4];
    float* out = (float*)d_out;

    const int smem_bytes = (QROWS * SPAD + 64 * 68 + 64 * 36) * sizeof(float);
    cudaFuncSetAttribute(qk_softmax_stats,
                         cudaFuncAttributeMaxDynamicSharedMemorySize, smem_bytes);

    qkv_gemm<<<dim3(THREEC / 64, MROWS / 64), 256>>>(x, qkv_w);
    qk_softmax_stats<<<dim3(NTOK / QROWS, BH), 256, smem_bytes>>>();
    finalize_mask<<<4, 256>>>(ce);
    av_gemm<<<dim3(NTOK / 64, BH), 256>>>();
    proj_gemm<<<dim3(CDIM / 64, MROWS / 64), 256>>>(proj_w, proj_b, out);
}

// round 5
// speedup vs baseline: 1.5903x; 1.5903x over previous
#include <cuda_runtime.h>
#include <math.h>

#define BDIM   4
#define NTOK   1024
#define CDIM   768
#define NH     12
#define HD     64
#define BH     (BDIM*NH)        // 48
#define MROWS  (BDIM*NTOK)      // 4096
#define THREEC (3*CDIM)         // 2304

#define BAND   64                       // rows per softmax/stats band
#define NCHUNK (BH*(NTOK/BAND))         // 768 partial-stat chunks

// -------- scratch (static device memory; no allocs allowed) --------
__device__ float g_q[BH*NTOK*HD];                 // [BH, N, hd]
__device__ float g_k[BH*NTOK*HD];
__device__ float g_v[BH*NTOK*HD];
__device__ float g_attn[(size_t)BH*NTOK*NTOK];    // scores -> probs in place
__device__ float g_ps[NCHUNK*NTOK];               // partial col sum(p)
__device__ float g_pp[NCHUNK*NTOK];               // partial col sum(p*logp)
__device__ float g_mask[NTOK];
__device__ int   g_kept[NTOK];
__device__ int   g_nkept;
__device__ float g_ctx[MROWS*CDIM];               // (attn*mask)@v in [B,N,C]

// ============================================================
// K1: qkv = x @ qkv_w.T ; scatter into g_q/g_k/g_v [BH,N,hd]
// ============================================================
__global__ void qkv_gemm(const float* __restrict__ x, const float* __restrict__ w) {
    __shared__ float As[16][65];
    __shared__ float Bs[16][65];
    const int m0 = blockIdx.y * 64;
    const int n0 = blockIdx.x * 64;
    const int tid = threadIdx.x;
    const int tx = tid & 15, ty = tid >> 4;
    float acc[4][4] = {};

    for (int k0 = 0; k0 < CDIM; k0 += 16) {
        for (int idx = tid; idx < 64 * 16; idx += 256) {
            int r = idx >> 4, c = idx & 15;
            As[c][r] = x[(m0 + r) * CDIM + k0 + c];
            Bs[c][r] = w[(n0 + r) * CDIM + k0 + c];
        }
        __syncthreads();
        #pragma unroll
        for (int kk = 0; kk < 16; kk++) {
            float a[4], b[4];
            #pragma unroll
            for (int i = 0; i < 4; i++) a[i] = As[kk][ty + 16 * i];
            #pragma unroll
            for (int j = 0; j < 4; j++) b[j] = Bs[kk][tx + 16 * j];
            #pragma unroll
            for (int i = 0; i < 4; i++)
                #pragma unroll
                for (int j = 0; j < 4; j++) acc[i][j] += a[i] * b[j];
        }
        __syncthreads();
    }
    const int b = m0 / NTOK;
    const int three = n0 / CDIM;
    const int h = (n0 % CDIM) / HD;
    float* dst = (three == 0) ? g_q : (three == 1) ? g_k : g_v;
    const int base = ((b * NH + h) * NTOK) * HD;
    #pragma unroll
    for (int i = 0; i < 4; i++) {
        int tok = (m0 % NTOK) + ty + 16 * i;
        #pragma unroll
        for (int j = 0; j < 4; j++) {
            int d = tx + 16 * j;
            dst[base + tok * HD + d] = acc[i][j];
        }
    }
}

// ============================================================
// K2: scores[bh,q,k] = scale * dot(q[bh,q,:], k[bh,k,:])
// ============================================================
__global__ void qk_gemm() {
    __shared__ float Qs[64][65];
    __shared__ float Ks[64][65];
    const int bh = blockIdx.z;
    const int q0 = blockIdx.y * 64;
    const int k0 = blockIdx.x * 64;
    const int tid = threadIdx.x;
    const int tx = tid & 15, ty = tid >> 4;
    const float* qb = g_q + (bh * NTOK + q0) * HD;
    const float* kb = g_k + (bh * NTOK + k0) * HD;
    for (int idx = tid; idx < 64 * 64; idx += 256) {
        int r = idx >> 6, c = idx & 63;
        Qs[r][c] = qb[r * HD + c];
        Ks[r][c] = kb[r * HD + c];
    }
    __syncthreads();
    float acc[4][4] = {};
    #pragma unroll 16
    for (int d = 0; d < 64; d++) {
        float a[4], b[4];
        #pragma unroll
        for (int i = 0; i < 4; i++) a[i] = Qs[ty + 16 * i][d];
        #pragma unroll
        for (int j = 0; j < 4; j++) b[j] = Ks[tx + 16 * j][d];
        #pragma unroll
        for (int i = 0; i < 4; i++)
            #pragma unroll
            for (int j = 0; j < 4; j++) acc[i][j] += a[i] * b[j];
    }
    const float scale = 0.125f;  // hd^-0.5
    #pragma unroll
    for (int i = 0; i < 4; i++) {
        size_t row = (size_t)(bh * NTOK + q0 + ty + 16 * i) * NTOK;
        #pragma unroll
        for (int j = 0; j < 4; j++)
            g_attn[row + k0 + tx + 16 * j] = acc[i][j] * scale;
    }
}

// ============================================================
// K3 (fused): row softmax (in place) + per-column band stats.
// Block = 256 thr, 64-row band of one bh. Tiny smem -> full occupancy.
// Pass 1: per-row lse (warp per row, coalesced). Pass 2: column pass
// writes p and accumulates col sum(p), sum(p*logp) for this band.
// ============================================================
__global__ void softmax_stats() {
    __shared__ float slse[BAND];
    const int bh = blockIdx.y;
    const int r0 = blockIdx.x * BAND;
    const int tid = threadIdx.x;
    const int wid = tid >> 5, lane = tid & 31;
    float* band = g_attn + ((size_t)bh * NTOK + r0) * NTOK;

    // pass 1: lse per row; warp w handles rows w, w+8, ...
    #pragma unroll
    for (int rr = 0; rr < BAND / 8; rr++) {
        const float* row = band + (size_t)(wid + 8 * rr) * NTOK;
        float m = -1e30f;
        #pragma unroll 8
        for (int i = 0; i < 32; i++) m = fmaxf(m, row[lane + 32 * i]);
        #pragma unroll
        for (int o = 16; o > 0; o >>= 1) m = fmaxf(m, __shfl_xor_sync(~0u, m, o));
        float s = 0.f;
        #pragma unroll 8
        for (int i = 0; i < 32; i++) s += __expf(row[lane + 32 * i] - m);
        #pragma unroll
        for (int o = 16; o > 0; o >>= 1) s += __shfl_xor_sync(~0u, s, o);
        if (lane == 0) slse[wid + 8 * rr] = m + __logf(s);
    }
    __syncthreads();

    // pass 2: column-oriented; thread owns cols tid+256k
    float ssum[4] = {0.f, 0.f, 0.f, 0.f};
    float psum[4] = {0.f, 0.f, 0.f, 0.f};
    for (int r = 0; r < BAND; r++) {
        float* row = band + (size_t)r * NTOK;
        const float l = slse[r];
        #pragma unroll
        for (int k = 0; k < 4; k++) {
            int col = tid + 256 * k;
            float lp = row[col] - l;
            float p = __expf(lp);
            ssum[k] += p;
            psum[k] += p * lp;
            row[col] = p;
        }
    }
    const int chunk = bh * (NTOK / BAND) + blockIdx.x;
    #pragma unroll
    for (int k = 0; k < 4; k++) {
        g_ps[chunk * NTOK + tid + 256 * k] = ssum[k];
        g_pp[chunk * NTOK + tid + 256 * k] = psum[k];
    }
}

// ============================================================
// K4: merge 768 band partials -> entropy -> mask
// ============================================================
__global__ void finalize_mask(const int* __restrict__ cur_epoch_ptr) {
    const int j = blockIdx.x * 128 + threadIdx.x;   // 0..1023
    float s = 0.f, pp = 0.f;
    #pragma unroll 8
    for (int c = 0; c < NCHUNK; c++) {
        s  += g_ps[c * NTOK + j];
        pp += g_pp[c * NTOK + j];
    }
    const int ce = *cur_epoch_ptr;
    float factor = 0.f;
    for (int i = 0; i < ce; i++) factor += expf(-(float)(i + 1));
    factor *= 5.0f;
    const float thr = logf((float)CDIM) - factor;
    const float ent = logf(s) - pp / s;
    g_mask[j] = (ent <= thr) ? 1.0f : 0.0f;
}

// ============================================================
// K5: compact kept columns (single block, exact prefix scan)
// ============================================================
__global__ void compact_kept() {
    __shared__ int sc[NTOK];
    const int tid = threadIdx.x;       // 1024 threads
    int m = (g_mask[tid] != 0.f) ? 1 : 0;
    sc[tid] = m;
    __syncthreads();
    // Hillis-Steele inclusive scan
    for (int o = 1; o < NTOK; o <<= 1) {
        int v = (tid >= o) ? sc[tid - o] : 0;
        __syncthreads();
        sc[tid] += v;
        __syncthreads();
    }
    if (m) g_kept[sc[tid] - 1] = tid;
    if (tid == NTOK - 1) g_nkept = sc[tid];
}

// ============================================================
// K6: ctx = attn[:, kept] @ v[kept, :]  (exact: dropped cols are zero)
// ============================================================
__global__ void av_gemm() {
    __shared__ int   kidx[16];
    __shared__ float Ps[64][17];
    __shared__ float Vs[16][65];
    const int bh = blockIdx.y;
    const int q0 = blockIdx.x * 64;
    const int tid = threadIdx.x;
    const int tx = tid & 15, ty = tid >> 4;
    const float* vb = g_v + bh * NTOK * HD;
    const float* pb = g_attn + (size_t)(bh * NTOK + q0) * NTOK;
    const int nk = g_nkept;
    float acc[4][4] = {};

    for (int t0 = 0; t0 < nk; t0 += 16) {
        if (tid < 16) {
            int i = t0 + tid;
            kidx[tid] = (i < nk) ? g_kept[i] : -1;
        }
        __syncthreads();
        for (int idx = tid; idx < 64 * 16; idx += 256) {
            int r = idx >> 4, c = idx & 15;
            int kc = kidx[c];
            Ps[r][c] = (kc >= 0) ? pb[(size_t)r * NTOK + kc] : 0.f;
        }
        for (int idx = tid; idx < 16 * 64; idx += 256) {
            int r = idx >> 6, c = idx & 63;
            int kc = kidx[r];
            Vs[r][c] = (kc >= 0) ? vb[kc * HD + c] : 0.f;
        }
        __syncthreads();
        #pragma unroll
        for (int kk = 0; kk < 16; kk++) {
            float a[4], b[4];
            #pragma unroll
            for (int i = 0; i < 4; i++) a[i] = Ps[ty + 16 * i][kk];
            #pragma unroll
            for (int j = 0; j < 4; j++) b[j] = Vs[kk][tx + 16 * j];
            #pragma unroll
            for (int i = 0; i < 4; i++)
                #pragma unroll
                for (int j = 0; j < 4; j++) acc[i][j] += a[i] * b[j];
        }
        __syncthreads();
    }
    const int b = bh / NH, h = bh % NH;
    #pragma unroll
    for (int i = 0; i < 4; i++) {
        int q = q0 + ty + 16 * i;
        #pragma unroll
        for (int j = 0; j < 4; j++) {
            int d = tx + 16 * j;
            g_ctx[(b * NTOK + q) * CDIM + h * HD + d] = acc[i][j];
        }
    }
}

// ============================================================
// K7: out = ctx @ proj_w.T + proj_b
// ============================================================
__global__ void proj_gemm(const float* __restrict__ w, const float* __restrict__ bias,
                          float* __restrict__ out) {
    __shared__ float As[16][65];
    __shared__ float Bs[16][65];
    const int m0 = blockIdx.y * 64;
    const int n0 = blockIdx.x * 64;
    const int tid = threadIdx.x;
    const int tx = tid & 15, ty = tid >> 4;
    float acc[4][4] = {};

    for (int k0 = 0; k0 < CDIM; k0 += 16) {
        for (int idx = tid; idx < 64 * 16; idx += 256) {
            int r = idx >> 4, c = idx & 15;
            As[c][r] = g_ctx[(m0 + r) * CDIM + k0 + c];
            Bs[c][r] = w[(n0 + r) * CDIM + k0 + c];
        }
        __syncthreads();
        #pragma unroll
        for (int kk = 0; kk < 16; kk++) {
            float a[4], b[4];
            #pragma unroll
            for (int i = 0; i < 4; i++) a[i] = As[kk][ty + 16 * i];
            #pragma unroll
            for (int j = 0; j < 4; j++) b[j] = Bs[kk][tx + 16 * j];
            #pragma unroll
            for (int i = 0; i < 4; i++)
                #pragma unroll
                for (int j = 0; j < 4; j++) acc[i][j] += a[i] * b[j];
        }
        __syncthreads();
    }
    #pragma unroll
    for (int i = 0; i < 4; i++) {
        int m = m0 + ty + 16 * i;
        #pragma unroll
        for (int j = 0; j < 4; j++) {
            int n = n0 + tx + 16 * j;
            out[m * CDIM + n] = acc[i][j] + bias[n];
        }
    }
}

// ============================================================
extern "C" void kernel_launch(void* const* d_in, const int* in_sizes, int n_in,
                              void* d_out, int out_size) {
    const float* x      = (const float*)d_in[0];
    const float* qkv_w  = (const float*)d_in[1];
    const float* proj_w = (const float*)d_in[2];
    const float* proj_b = (const float*)d_in[3];
    const int*   ce     = (const int*)d_in[4];
    float* out = (float*)d_out;

    qkv_gemm<<<dim3(THREEC / 64, MROWS / 64), 256>>>(x, qkv_w);
    qk_gemm<<<dim3(NTOK / 64, NTOK / 64, BH), 256>>>();
    softmax_stats<<<dim3(NTOK / BAND, BH), 256>>>();
    finalize_mask<<<8, 128>>>(ce);
    compact_kept<<<1, 1024>>>();
    av_gemm<<<dim3(NTOK / 64, BH), 256>>>();
    proj_gemm<<<dim3(CDIM / 64, MROWS / 64), 256>>>(proj_w, proj_b, out);
}

// round 6
// speedup vs baseline: 3.9222x; 2.4664x over previous
#include <cuda_runtime.h>
#include <math.h>

#define BDIM   4
#define NTOK   1024
#define CDIM   768
#define NH     12
#define HD     64
#define BH     (BDIM*NH)        // 48
#define MROWS  (BDIM*NTOK)      // 4096
#define THREEC (3*CDIM)         // 2304

#define BAND   64
#define NCHUNK (BH*(NTOK/BAND))         // 768

// -------- scratch (static device memory; no allocs allowed) --------
__device__ float g_q[BH*NTOK*HD];
__device__ float g_k[BH*NTOK*HD];
__device__ float g_v[BH*NTOK*HD];
__device__ float g_attn[(size_t)BH*NTOK*NTOK];    // raw scaled scores (never rewritten)
__device__ float g_lse[BH*NTOK];                  // per-row logsumexp
__device__ float g_ps[NCHUNK*NTOK];
__device__ float g_pp[NCHUNK*NTOK];
__device__ float g_mask[NTOK];
__device__ int   g_kept[NTOK];
__device__ int   g_nkept;
__device__ float g_ctx[MROWS*CDIM];

// ============================================================
// tf32 warp-MMA building blocks
// ============================================================
__device__ __forceinline__ unsigned f2tf(float f) {
    unsigned u; asm("cvt.rna.tf32.f32 %0, %1;" : "=r"(u) : "f"(f)); return u;
}
__device__ __forceinline__ void mma8(float d[4], const unsigned a[4], const unsigned b[2]) {
    asm volatile(
        "mma.sync.aligned.m16n8k8.row.col.f32.tf32.tf32.f32 "
        "{%0,%1,%2,%3}, {%4,%5,%6,%7}, {%8,%9}, {%0,%1,%2,%3};\n"
        : "+f"(d[0]), "+f"(d[1]), "+f"(d[2]), "+f"(d[3])
        : "r"(a[0]), "r"(a[1]), "r"(a[2]), "r"(a[3]), "r"(b[0]), "r"(b[1]));
}

#define APITCH 136   // 136 % 32 == 8 -> conflict-free fragment loads
#define BPITCH 72    // 72  % 32 == 8

// C[128,64] tile of A[M,K](row) @ B[N,K](row)^T ; both lda = ldb = K.
__device__ __forceinline__ void mma_tiles(
    const float* __restrict__ A, const float* __restrict__ B,
    int K, int m0, int n0, float acc[2][4][4],
    unsigned* As, unsigned* Bs)
{
    const int tid = threadIdx.x;
    const int lane = tid & 31, wid = tid >> 5;
    const int wm = wid >> 1, wn = wid & 1;         // 4 x 2 warp grid
    const int g = lane >> 2, tig = lane & 3;
    const int lr = tid >> 2;                       // 0..63
    const int c4 = (tid & 3) * 4;

    for (int k0 = 0; k0 < K; k0 += 16) {
        __syncthreads();
        #pragma unroll
        for (int rr = 0; rr < 2; rr++) {
            const float4 v = *(const float4*)(A + (size_t)(m0 + lr + 64 * rr) * K + k0 + c4);
            As[(c4 + 0) * APITCH + lr + 64 * rr] = f2tf(v.x);
            As[(c4 + 1) * APITCH + lr + 64 * rr] = f2tf(v.y);
            As[(c4 + 2) * APITCH + lr + 64 * rr] = f2tf(v.z);
            As[(c4 + 3) * APITCH + lr + 64 * rr] = f2tf(v.w);
        }
        {
            const float4 v = *(const float4*)(B + (size_t)(n0 + lr) * K + k0 + c4);
            Bs[(c4 + 0) * BPITCH + lr] = f2tf(v.x);
            Bs[(c4 + 1) * BPITCH + lr] = f2tf(v.y);
            Bs[(c4 + 2) * BPITCH + lr] = f2tf(v.z);
            Bs[(c4 + 3) * BPITCH + lr] = f2tf(v.w);
        }
        __syncthreads();
        #pragma unroll
        for (int kk = 0; kk < 16; kk += 8) {
            unsigned a[2][4], b[4][2];
            #pragma unroll
            for (int mi = 0; mi < 2; mi++) {
                int row = wm * 32 + mi * 16 + g;
                a[mi][0] = As[(kk + tig) * APITCH + row];
                a[mi][1] = As[(kk + tig) * APITCH + row + 8];
                a[mi][2] = As[(kk + tig + 4) * APITCH + row];
                a[mi][3] = As[(kk + tig + 4) * APITCH + row + 8];
            }
            #pragma unroll
            for (int nj = 0; nj < 4; nj++) {
                int col = wn * 32 + nj * 8 + g;
                b[nj][0] = Bs[(kk + tig) * BPITCH + col];
                b[nj][1] = Bs[(kk + tig + 4) * BPITCH + col];
            }
            #pragma unroll
            for (int mi = 0; mi < 2; mi++)
                #pragma unroll
                for (int nj = 0; nj < 4; nj++)
                    mma8(acc[mi][nj], a[mi], b[nj]);
        }
    }
}

// ============================================================
// K1: qkv = x @ qkv_w.T (tf32 MMA) ; scatter into g_q/g_k/g_v
// ============================================================
__global__ void qkv_mma(const float* __restrict__ x, const float* __restrict__ w) {
    __shared__ unsigned As[16 * APITCH];
    __shared__ unsigned Bs[16 * BPITCH];
    float acc[2][4][4] = {};
    const int m0 = blockIdx.y * 128, n0 = blockIdx.x * 64;
    mma_tiles(x, w, CDIM, m0, n0, acc, As, Bs);

    const int tid = threadIdx.x, lane = tid & 31, wid = tid >> 5;
    const int wm = wid >> 1, wn = wid & 1, g = lane >> 2, tig = lane & 3;
    const int b = m0 / NTOK;
    const int three = n0 / CDIM;
    const int h = (n0 % CDIM) / HD;
    float* dst = (three == 0) ? g_q : (three == 1) ? g_k : g_v;
    const size_t base = (size_t)(b * NH + h) * NTOK * HD;
    #pragma unroll
    for (int mi = 0; mi < 2; mi++)
        #pragma unroll
        for (int e2 = 0; e2 < 2; e2++) {
            int tok = (m0 % NTOK) + wm * 32 + mi * 16 + g + 8 * e2;
            #pragma unroll
            for (int nj = 0; nj < 4; nj++) {
                int d0 = wn * 32 + nj * 8 + tig * 2;
                *(float2*)(dst + base + (size_t)tok * HD + d0) =
                    make_float2(acc[mi][nj][e2 * 2], acc[mi][nj][e2 * 2 + 1]);
            }
        }
}

// ============================================================
// K2: scores = scale * q @ k^T (tf32 MMA), per bh
// ============================================================
__global__ void qk_mma() {
    __shared__ unsigned As[16 * APITCH];
    __shared__ unsigned Bs[16 * BPITCH];
    float acc[2][4][4] = {};
    const int bh = blockIdx.z;
    const int m0 = blockIdx.y * 128, n0 = blockIdx.x * 64;
    const float* qb = g_q + (size_t)bh * NTOK * HD;
    const float* kb = g_k + (size_t)bh * NTOK * HD;
    mma_tiles(qb, kb, HD, m0, n0, acc, As, Bs);

    const int tid = threadIdx.x, lane = tid & 31, wid = tid >> 5;
    const int wm = wid >> 1, wn = wid & 1, g = lane >> 2, tig = lane & 3;
    const float scale = 0.125f;
    #pragma unroll
    for (int mi = 0; mi < 2; mi++)
        #pragma unroll
        for (int e2 = 0; e2 < 2; e2++) {
            int q = m0 + wm * 32 + mi * 16 + g + 8 * e2;
            size_t rowoff = ((size_t)bh * NTOK + q) * NTOK;
            #pragma unroll
            for (int nj = 0; nj < 4; nj++) {
                int n = n0 + wn * 32 + nj * 8 + tig * 2;
                *(float2*)(g_attn + rowoff + n) =
                    make_float2(acc[mi][nj][e2 * 2] * scale, acc[mi][nj][e2 * 2 + 1] * scale);
            }
        }
}

// ============================================================
// K3: pass1 per-row lse (stored, scores untouched);
//     pass2 column stats from scores (no prob write)
// ============================================================
__global__ void softmax_stats() {
    __shared__ float slse[BAND];
    const int bh = blockIdx.y;
    const int r0 = blockIdx.x * BAND;
    const int tid = threadIdx.x;
    const int wid = tid >> 5, lane = tid & 31;
    float* band = g_attn + ((size_t)bh * NTOK + r0) * NTOK;

    #pragma unroll
    for (int rr = 0; rr < BAND / 8; rr++) {
        const float* row = band + (size_t)(wid + 8 * rr) * NTOK;
        float m = -1e30f;
        #pragma unroll 8
        for (int i = 0; i < 32; i++) m = fmaxf(m, row[lane + 32 * i]);
        #pragma unroll
        for (int o = 16; o > 0; o >>= 1) m = fmaxf(m, __shfl_xor_sync(~0u, m, o));
        float s = 0.f;
        #pragma unroll 8
        for (int i = 0; i < 32; i++) s += __expf(row[lane + 32 * i] - m);
        #pragma unroll
        for (int o = 16; o > 0; o >>= 1) s += __shfl_xor_sync(~0u, s, o);
        if (lane == 0) {
            float l = m + __logf(s);
            slse[wid + 8 * rr] = l;
            g_lse[bh * NTOK + r0 + wid + 8 * rr] = l;
        }
    }
    __syncthreads();

    float ssum[4] = {0.f, 0.f, 0.f, 0.f};
    float psum[4] = {0.f, 0.f, 0.f, 0.f};
    for (int r = 0; r < BAND; r++) {
        const float* row = band + (size_t)r * NTOK;
        const float l = slse[r];
        #pragma unroll
        for (int k = 0; k < 4; k++) {
            float lp = row[tid + 256 * k] - l;
            float p = __expf(lp);
            ssum[k] += p;
            psum[k] += p * lp;
        }
    }
    const int chunk = bh * (NTOK / BAND) + blockIdx.x;
    #pragma unroll
    for (int k = 0; k < 4; k++) {
        g_ps[chunk * NTOK + tid + 256 * k] = ssum[k];
        g_pp[chunk * NTOK + tid + 256 * k] = psum[k];
    }
}

// ============================================================
// K4: merge partials -> entropy -> mask (block per column)
// ============================================================
__global__ void finalize_mask(const int* __restrict__ cur_epoch_ptr) {
    __shared__ float rs[256], rp[256];
    const int j = blockIdx.x;          // 0..1023
    const int tid = threadIdx.x;       // 256
    float s = 0.f, pp = 0.f;
    for (int c = tid; c < NCHUNK; c += 256) {
        s  += g_ps[c * NTOK + j];
        pp += g_pp[c * NTOK + j];
    }
    rs[tid] = s; rp[tid] = pp;
    __syncthreads();
    for (int o = 128; o > 0; o >>= 1) {
        if (tid < o) { rs[tid] += rs[tid + o]; rp[tid] += rp[tid + o]; }
        __syncthreads();
    }
    if (tid == 0) {
        float S = rs[0], PP = rp[0];
        const int ce = *cur_epoch_ptr;
        float factor = 0.f;
        for (int i = 0; i < ce; i++) factor += expf(-(float)(i + 1));
        factor *= 5.0f;
        const float thr = logf((float)CDIM) - factor;
        const float ent = logf(S) - PP / S;
        g_mask[j] = (ent <= thr) ? 1.0f : 0.0f;
    }
}

// ============================================================
// K5: compact kept columns (single block, prefix scan)
// ============================================================
__global__ void compact_kept() {
    __shared__ int sc[NTOK];
    const int tid = threadIdx.x;       // 1024 threads
    int m = (g_mask[tid] != 0.f) ? 1 : 0;
    sc[tid] = m;
    __syncthreads();
    for (int o = 1; o < NTOK; o <<= 1) {
        int v = (tid >= o) ? sc[tid - o] : 0;
        __syncthreads();
        sc[tid] += v;
        __syncthreads();
    }
    if (m) g_kept[sc[tid] - 1] = tid;
    if (tid == NTOK - 1) g_nkept = sc[tid];
}

// ============================================================
// K6: ctx = p[:, kept] @ v[kept, :] ; p recomputed from scores+lse
// ============================================================
__global__ void av_gemm() {
    __shared__ int   kidx[16];
    __shared__ float srow_lse[64];
    __shared__ float Ps[64][17];
    __shared__ float Vs[16][65];
    const int bh = blockIdx.y;
    const int q0 = blockIdx.x * 64;
    const int tid = threadIdx.x;
    const int tx = tid & 15, ty = tid >> 4;
    const float* vb = g_v + (size_t)bh * NTOK * HD;
    const float* pb = g_attn + (size_t)(bh * NTOK + q0) * NTOK;
    if (tid < 64) srow_lse[tid] = g_lse[bh * NTOK + q0 + tid];
    const int nk = g_nkept;
    float acc[4][4] = {};
    __syncthreads();

    for (int t0 = 0; t0 < nk; t0 += 16) {
        if (tid < 16) {
            int i = t0 + tid;
            kidx[tid] = (i < nk) ? g_kept[i] : -1;
        }
        __syncthreads();
        for (int idx = tid; idx < 64 * 16; idx += 256) {
            int r = idx >> 4, c = idx & 15;
            int kc = kidx[c];
            Ps[r][c] = (kc >= 0) ? __expf(pb[(size_t)r * NTOK + kc] - srow_lse[r]) : 0.f;
        }
        for (int idx = tid; idx < 16 * 64; idx += 256) {
            int r = idx >> 6, c = idx & 63;
            int kc = kidx[r];
            Vs[r][c] = (kc >= 0) ? vb[kc * HD + c] : 0.f;
        }
        __syncthreads();
        #pragma unroll
        for (int kk = 0; kk < 16; kk++) {
            float a[4], b[4];
            #pragma unroll
            for (int i = 0; i < 4; i++) a[i] = Ps[ty + 16 * i][kk];
            #pragma unroll
            for (int j = 0; j < 4; j++) b[j] = Vs[kk][tx + 16 * j];
            #pragma unroll
            for (int i = 0; i < 4; i++)
                #pragma unroll
                for (int j = 0; j < 4; j++) acc[i][j] += a[i] * b[j];
        }
        __syncthreads();
    }
    const int b = bh / NH, h = bh % NH;
    #pragma unroll
    for (int i = 0; i < 4; i++) {
        int q = q0 + ty + 16 * i;
        #pragma unroll
        for (int j = 0; j < 4; j++) {
            int d = tx + 16 * j;
            g_ctx[(b * NTOK + q) * CDIM + h * HD + d] = acc[i][j];
        }
    }
}

// ============================================================
// K7: out = ctx @ proj_w.T + proj_b (tf32 MMA)
// ============================================================
__global__ void proj_mma(const float* __restrict__ w, const float* __restrict__ bias,
                         float* __restrict__ out) {
    __shared__ unsigned As[16 * APITCH];
    __shared__ unsigned Bs[16 * BPITCH];
    float acc[2][4][4] = {};
    const int m0 = blockIdx.y * 128, n0 = blockIdx.x * 64;
    mma_tiles(g_ctx, w, CDIM, m0, n0, acc, As, Bs);

    const int tid = threadIdx.x, lane = tid & 31, wid = tid >> 5;
    const int wm = wid >> 1, wn = wid & 1, g = lane >> 2, tig = lane & 3;
    #pragma unroll
    for (int mi = 0; mi < 2; mi++)
        #pragma unroll
        for (int e2 = 0; e2 < 2; e2++) {
            int m = m0 + wm * 32 + mi * 16 + g + 8 * e2;
            #pragma unroll
            for (int nj = 0; nj < 4; nj++) {
                int n = n0 + wn * 32 + nj * 8 + tig * 2;
                *(float2*)(out + (size_t)m * CDIM + n) =
                    make_float2(acc[mi][nj][e2 * 2] + bias[n],
                                acc[mi][nj][e2 * 2 + 1] + bias[n + 1]);
            }
        }
}

// ============================================================
extern "C" void kernel_launch(void* const* d_in, const int* in_sizes, int n_in,
                              void* d_out, int out_size) {
    const float* x      = (const float*)d_in[0];
    const float* qkv_w  = (const float*)d_in[1];
    const float* proj_w = (const float*)d_in[2];
    const float* proj_b = (const float*)d_in[3];
    const int*   ce     = (const int*)d_in[4];
    float* out = (float*)d_out;

    qkv_mma<<<dim3(THREEC / 64, MROWS / 128), 256>>>(x, qkv_w);
    qk_mma<<<dim3(NTOK / 64, NTOK / 128, BH), 256>>>();
    softmax_stats<<<dim3(NTOK / BAND, BH), 256>>>();
    finalize_mask<<<NTOK, 256>>>(ce);
    compact_kept<<<1, 1024>>>();
    av_gemm<<<dim3(NTOK / 64, BH), 256>>>();
    proj_mma<<<dim3(CDIM / 64, MROWS / 128), 256>>>(proj_w, proj_b, out);
}

// round 8
// speedup vs baseline: 4.0879x; 1.0423x over previous
#include <cuda_runtime.h>
#include <math.h>

#define BDIM   4
#define NTOK   1024
#define CDIM   768
#define NH     12
#define HD     64
#define BH     (BDIM*NH)        // 48
#define MROWS  (BDIM*NTOK)      // 4096
#define THREEC (3*CDIM)         // 2304

#define MTILES (NTOK/128)               // 8 m-tiles per bh
#define NCHUNK (BH*MTILES)              // 384 column-stat chunks

// -------- scratch (static device memory; no allocs allowed) --------
__device__ float g_q[BH*NTOK*HD];
__device__ float g_k[BH*NTOK*HD];
__device__ float g_v[BH*NTOK*HD];
__device__ float g_lse[BH*NTOK];
__device__ float g_ps[NCHUNK*NTOK];
__device__ float g_pp[NCHUNK*NTOK];
__device__ float g_mask[NTOK];
__device__ int   g_kept[NTOK];
__device__ int   g_nkept;
__device__ float g_ctx[MROWS*CDIM];

// ============================================================
// tf32 warp-MMA building blocks
// ============================================================
__device__ __forceinline__ unsigned f2tf(float f) {
    unsigned u; asm("cvt.rna.tf32.f32 %0, %1;" : "=r"(u) : "f"(f)); return u;
}
__device__ __forceinline__ void mma8(float d[4], const unsigned a[4], const unsigned b[2]) {
    asm volatile(
        "mma.sync.aligned.m16n8k8.row.col.f32.tf32.tf32.f32 "
        "{%0,%1,%2,%3}, {%4,%5,%6,%7}, {%8,%9}, {%0,%1,%2,%3};\n"
        : "+f"(d[0]), "+f"(d[1]), "+f"(d[2]), "+f"(d[3])
        : "r"(a[0]), "r"(a[1]), "r"(a[2]), "r"(a[3]), "r"(b[0]), "r"(b[1]));
}

// ------- K-chunked GEMM path (qkv / proj) -------
#define APITCH 136
#define BPITCH 72

__device__ __forceinline__ void mma_tiles(
    const float* __restrict__ A, const float* __restrict__ B,
    int K, int m0, int n0, float acc[2][4][4],
    unsigned* As, unsigned* Bs)
{
    const int tid = threadIdx.x;
    const int lane = tid & 31, wid = tid >> 5;
    const int wm = wid >> 1, wn = wid & 1;
    const int g = lane >> 2, tig = lane & 3;
    const int lr = tid >> 2;
    const int c4 = (tid & 3) * 4;

    for (int k0 = 0; k0 < K; k0 += 16) {
        __syncthreads();
        #pragma unroll
        for (int rr = 0; rr < 2; rr++) {
            const float4 v = *(const float4*)(A + (size_t)(m0 + lr + 64 * rr) * K + k0 + c4);
            As[(c4 + 0) * APITCH + lr + 64 * rr] = f2tf(v.x);
            As[(c4 + 1) * APITCH + lr + 64 * rr] = f2tf(v.y);
            As[(c4 + 2) * APITCH + lr + 64 * rr] = f2tf(v.z);
            As[(c4 + 3) * APITCH + lr + 64 * rr] = f2tf(v.w);
        }
        {
            const float4 v = *(const float4*)(B + (size_t)(n0 + lr) * K + k0 + c4);
            Bs[(c4 + 0) * BPITCH + lr] = f2tf(v.x);
            Bs[(c4 + 1) * BPITCH + lr] = f2tf(v.y);
            Bs[(c4 + 2) * BPITCH + lr] = f2tf(v.z);
            Bs[(c4 + 3) * BPITCH + lr] = f2tf(v.w);
        }
        __syncthreads();
        #pragma unroll
        for (int kk = 0; kk < 16; kk += 8) {
            unsigned a[2][4], b[4][2];
            #pragma unroll
            for (int mi = 0; mi < 2; mi++) {
                int row = wm * 32 + mi * 16 + g;
                a[mi][0] = As[(kk + tig) * APITCH + row];
                a[mi][1] = As[(kk + tig) * APITCH + row + 8];
                a[mi][2] = As[(kk + tig + 4) * APITCH + row];
                a[mi][3] = As[(kk + tig + 4) * APITCH + row + 8];
            }
            #pragma unroll
            for (int nj = 0; nj < 4; nj++) {
                int col = wn * 32 + nj * 8 + g;
                b[nj][0] = Bs[(kk + tig) * BPITCH + col];
                b[nj][1] = Bs[(kk + tig + 4) * BPITCH + col];
            }
            #pragma unroll
            for (int mi = 0; mi < 2; mi++)
                #pragma unroll
                for (int nj = 0; nj < 4; nj++)
                    mma8(acc[mi][nj], a[mi], b[nj]);
        }
    }
}

// ============================================================
// K1: qkv = x @ qkv_w.T (tf32 MMA) ; scatter into g_q/g_k/g_v
// ============================================================
__global__ void qkv_mma(const float* __restrict__ x, const float* __restrict__ w) {
    __shared__ unsigned As[16 * APITCH];
    __shared__ unsigned Bs[16 * BPITCH];
    float acc[2][4][4] = {};
    const int m0 = blockIdx.y * 128, n0 = blockIdx.x * 64;
    mma_tiles(x, w, CDIM, m0, n0, acc, As, Bs);

    const int tid = threadIdx.x, lane = tid & 31, wid = tid >> 5;
    const int wm = wid >> 1, wn = wid & 1, g = lane >> 2, tig = lane & 3;
    const int b = m0 / NTOK;
    const int three = n0 / CDIM;
    const int h = (n0 % CDIM) / HD;
    float* dst = (three == 0) ? g_q : (three == 1) ? g_k : g_v;
    const size_t base = (size_t)(b * NH + h) * NTOK * HD;
    #pragma unroll
    for (int mi = 0; mi < 2; mi++)
        #pragma unroll
        for (int e2 = 0; e2 < 2; e2++) {
            int tok = (m0 % NTOK) + wm * 32 + mi * 16 + g + 8 * e2;
            #pragma unroll
            for (int nj = 0; nj < 4; nj++) {
                int d0 = wn * 32 + nj * 8 + tig * 2;
                *(float2*)(dst + base + (size_t)tok * HD + d0) =
                    make_float2(acc[mi][nj][e2 * 2], acc[mi][nj][e2 * 2 + 1]);
            }
        }
}

// ============================================================
// Persistent-Q attention MMA staging (row-major, pitch 72)
// ============================================================
#define AP 72

__device__ __forceinline__ void load_q_tile(const float* qb, int m0, unsigned* As, int tid) {
    for (int i = tid; i < 128 * 16; i += 256) {
        int row = i >> 4, k4 = (i & 15) << 2;
        const float4 v = *(const float4*)(qb + (size_t)(m0 + row) * HD + k4);
        As[row * AP + k4 + 0] = f2tf(v.x);
        As[row * AP + k4 + 1] = f2tf(v.y);
        As[row * AP + k4 + 2] = f2tf(v.z);
        As[row * AP + k4 + 3] = f2tf(v.w);
    }
}
__device__ __forceinline__ void load_k_tile(const float* kb, int n0, unsigned* Bs, int tid) {
    for (int i = tid; i < 64 * 16; i += 256) {
        int col = i >> 4, k4 = (i & 15) << 2;
        const float4 v = *(const float4*)(kb + (size_t)(n0 + col) * HD + k4);
        Bs[col * AP + k4 + 0] = f2tf(v.x);
        Bs[col * AP + k4 + 1] = f2tf(v.y);
        Bs[col * AP + k4 + 2] = f2tf(v.z);
        Bs[col * AP + k4 + 3] = f2tf(v.w);
    }
}
__device__ __forceinline__ void qk_mma_tile(
    const unsigned* As, const unsigned* Bs, float acc[2][4][4],
    int wm, int wn, int g, int tig)
{
    #pragma unroll
    for (int kk = 0; kk < 64; kk += 8) {
        unsigned a[2][4], b[4][2];
        #pragma unroll
        for (int mi = 0; mi < 2; mi++) {
            int row = wm * 32 + mi * 16 + g;
            a[mi][0] = As[row * AP + kk + tig];
            a[mi][1] = As[(row + 8) * AP + kk + tig];
            a[mi][2] = As[row * AP + kk + tig + 4];
            a[mi][3] = As[(row + 8) * AP + kk + tig + 4];
        }
        #pragma unroll
        for (int nj = 0; nj < 4; nj++) {
            int col = wn * 32 + nj * 8 + g;
            b[nj][0] = Bs[col * AP + kk + tig];
            b[nj][1] = Bs[col * AP + kk + tig + 4];
        }
        #pragma unroll
        for (int mi = 0; mi < 2; mi++)
            #pragma unroll
            for (int nj = 0; nj < 4; nj++)
                mma8(acc[mi][nj], a[mi], b[nj]);
    }
}

// ============================================================
// K2: QK^T with online-softmax epilogue -> g_lse (no score write)
// ============================================================
__global__ void qk_lse() {
    extern __shared__ unsigned sh[];
    unsigned* As = sh;                 // [128][AP]
    unsigned* Bs = sh + 128 * AP;      // [64][AP]
    __shared__ float sm_m[128 * 2];
    __shared__ float sm_s[128 * 2];

    const int bh = blockIdx.y;
    const int m0 = blockIdx.x * 128;
    const int tid = threadIdx.x, lane = tid & 31, wid = tid >> 5;
    const int wm = wid >> 1, wn = wid & 1, g = lane >> 2, tig = lane & 3;
    const float* qb = g_q + (size_t)bh * NTOK * HD;
    const float* kb = g_k + (size_t)bh * NTOK * HD;

    load_q_tile(qb, m0, As, tid);

    float mrun[2][2] = {{-1e30f, -1e30f}, {-1e30f, -1e30f}};
    float srun[2][2] = {};

    for (int n0 = 0; n0 < NTOK; n0 += 64) {
        __syncthreads();
        load_k_tile(kb, n0, Bs, tid);
        __syncthreads();
        float acc[2][4][4] = {};
        qk_mma_tile(As, Bs, acc, wm, wn, g, tig);

        #pragma unroll
        for (int mi = 0; mi < 2; mi++)
            #pragma unroll
            for (int e = 0; e < 2; e++) {
                float v[8];
                #pragma unroll
                for (int nj = 0; nj < 4; nj++) {
                    v[nj * 2]     = acc[mi][nj][e * 2] * 0.125f;
                    v[nj * 2 + 1] = acc[mi][nj][e * 2 + 1] * 0.125f;
                }
                float mt = v[0];
                #pragma unroll
                for (int j = 1; j < 8; j++) mt = fmaxf(mt, v[j]);
                mt = fmaxf(mt, __shfl_xor_sync(~0u, mt, 1));
                mt = fmaxf(mt, __shfl_xor_sync(~0u, mt, 2));
                float mo = mrun[mi][e];
                float mn = fmaxf(mo, mt);
                float s = 0.f;
                #pragma unroll
                for (int j = 0; j < 8; j++) s += __expf(v[j] - mn);
                s += __shfl_xor_sync(~0u, s, 1);
                s += __shfl_xor_sync(~0u, s, 2);
                srun[mi][e] = srun[mi][e] * __expf(mo - mn) + s;
                mrun[mi][e] = mn;
            }
    }
    if (tig == 0) {
        #pragma unroll
        for (int mi = 0; mi < 2; mi++)
            #pragma unroll
            for (int e = 0; e < 2; e++) {
                int row = wm * 32 + mi * 16 + g + 8 * e;
                sm_m[row * 2 + wn] = mrun[mi][e];
                sm_s[row * 2 + wn] = srun[mi][e];
            }
    }
    __syncthreads();
    if (tid < 128) {
        float m0v = sm_m[tid * 2], m1v = sm_m[tid * 2 + 1];
        float M = fmaxf(m0v, m1v);
        float S = sm_s[tid * 2] * __expf(m0v - M) + sm_s[tid * 2 + 1] * __expf(m1v - M);
        g_lse[bh * NTOK + m0 + tid] = M + __logf(S);
    }
}

// ============================================================
// K3: re-run identical QK^T, per-column stats from registers
// ============================================================
__global__ void qk_stats() {
    extern __shared__ unsigned sh[];
    unsigned* As = sh;
    unsigned* Bs = sh + 128 * AP;
    __shared__ float slse[128];
    __shared__ float cs[4][64];
    __shared__ float cp[4][64];

    const int bh = blockIdx.y;
    const int m0 = blockIdx.x * 128;
    const int tid = threadIdx.x, lane = tid & 31, wid = tid >> 5;
    const int wm = wid >> 1, wn = wid & 1, g = lane >> 2, tig = lane & 3;
    const float* qb = g_q + (size_t)bh * NTOK * HD;
    const float* kb = g_k + (size_t)bh * NTOK * HD;
    const int chunk = bh * MTILES + blockIdx.x;

    load_q_tile(qb, m0, As, tid);
    if (tid < 128) slse[tid] = g_lse[bh * NTOK + m0 + tid];

    for (int n0 = 0; n0 < NTOK; n0 += 64) {
        __syncthreads();
        load_k_tile(kb, n0, Bs, tid);
        __syncthreads();
        float acc[2][4][4] = {};
        qk_mma_tile(As, Bs, acc, wm, wn, g, tig);

        float colS[8] = {}, colP[8] = {};
        #pragma unroll
        for (int mi = 0; mi < 2; mi++)
            #pragma unroll
            for (int e = 0; e < 2; e++) {
                int row = wm * 32 + mi * 16 + g + 8 * e;
                float l = slse[row];
                #pragma unroll
                for (int nj = 0; nj < 4; nj++)
                    #pragma unroll
                    for (int c = 0; c < 2; c++) {
                        float lp = acc[mi][nj][e * 2 + c] * 0.125f - l;
                        float p = __expf(lp);
                        colS[nj * 2 + c] += p;
                        colP[nj * 2 + c] += p * lp;
                    }
            }
        #pragma unroll
        for (int j = 0; j < 8; j++) {
            #pragma unroll
            for (int o = 4; o < 32; o <<= 1) {
                colS[j] += __shfl_xor_sync(~0u, colS[j], o);
                colP[j] += __shfl_xor_sync(~0u, colP[j], o);
            }
        }
        if (g == 0) {
            #pragma unroll
            for (int nj = 0; nj < 4; nj++)
                #pragma unroll
                for (int c = 0; c < 2; c++) {
                    int col = wn * 32 + nj * 8 + 2 * tig + c;
                    cs[wm][col] = colS[nj * 2 + c];
                    cp[wm][col] = colP[nj * 2 + c];
                }
        }
        __syncthreads();
        if (tid < 64) {
            g_ps[chunk * NTOK + n0 + tid] = cs[0][tid] + cs[1][tid] + cs[2][tid] + cs[3][tid];
            g_pp[chunk * NTOK + n0 + tid] = cp[0][tid] + cp[1][tid] + cp[2][tid] + cp[3][tid];
        }
    }
}

// ============================================================
// K4: merge 384 partials -> entropy -> mask (block per column)
// ============================================================
__global__ void finalize_mask(const int* __restrict__ cur_epoch_ptr) {
    __shared__ float rs[128], rp[128];
    const int j = blockIdx.x;
    const int tid = threadIdx.x;       // 128
    float s = 0.f, pp = 0.f;
    for (int c = tid; c < NCHUNK; c += 128) {
        s  += g_ps[c * NTOK + j];
        pp += g_pp[c * NTOK + j];
    }
    rs[tid] = s; rp[tid] = pp;
    __syncthreads();
    for (int o = 64; o > 0; o >>= 1) {
        if (tid < o) { rs[tid] += rs[tid + o]; rp[tid] += rp[tid + o]; }
        __syncthreads();
    }
    if (tid == 0) {
        float S = rs[0], PP = rp[0];
        const int ce = *cur_epoch_ptr;
        float factor = 0.f;
        for (int i = 0; i < ce; i++) factor += expf(-(float)(i + 1));
        factor *= 5.0f;
        const float thr = logf((float)CDIM) - factor;
        const float ent = logf(S) - PP / S;
        g_mask[j] = (ent <= thr) ? 1.0f : 0.0f;
    }
}

// ============================================================
// K5: compact kept columns
// ============================================================
__global__ void compact_kept() {
    __shared__ int sc[NTOK];
    const int tid = threadIdx.x;
    int m = (g_mask[tid] != 0.f) ? 1 : 0;
    sc[tid] = m;
    __syncthreads();
    for (int o = 1; o < NTOK; o <<= 1) {
        int v = (tid >= o) ? sc[tid - o] : 0;
        __syncthreads();
        sc[tid] += v;
        __syncthreads();
    }
    if (m) g_kept[sc[tid] - 1] = tid;
    if (tid == NTOK - 1) g_nkept = sc[tid];
}

// ============================================================
// K6: ctx = p[:,kept] @ v[kept,:] ; scores recomputed on the fly
// (Qs pitch 68: row stride 272 B = 16B multiple -> float4-safe)
// ============================================================
__global__ void av_sparse() {
    __shared__ int   kidx[16];
    __shared__ float Qs[64][68];
    __shared__ float Ks[16][65];
    __shared__ float Vs[16][65];
    __shared__ float Ps[64][17];
    __shared__ float slse[64];
    const int bh = blockIdx.y;
    const int q0 = blockIdx.x * 64;
    const int tid = threadIdx.x;
    const int tx = tid & 15, ty = tid >> 4;
    const float* qb = g_q + (size_t)bh * NTOK * HD;
    const float* kb = g_k + (size_t)bh * NTOK * HD;
    const float* vb = g_v + (size_t)bh * NTOK * HD;

    for (int i = tid; i < 64 * 16; i += 256) {
        int r = i >> 4, k4 = (i & 15) << 2;
        const float4 v = *(const float4*)(qb + (size_t)(q0 + r) * HD + k4);
        *(float4*)(&Qs[r][k4]) = v;
    }
    if (tid < 64) slse[tid] = g_lse[bh * NTOK + q0 + tid];
    const int nk = g_nkept;
    float acc[4][4] = {};

    for (int t0 = 0; t0 < nk; t0 += 16) {
        __syncthreads();
        if (tid < 16) {
            int i = t0 + tid;
            kidx[tid] = (i < nk) ? g_kept[i] : -1;
        }
        __syncthreads();
        for (int i = tid; i < 16 * 64; i += 256) {
            int c = i >> 6, d = i & 63;
            int kc = kidx[c];
            Ks[c][d] = (kc >= 0) ? kb[(size_t)kc * HD + d] : 0.f;
            Vs[c][d] = (kc >= 0) ? vb[(size_t)kc * HD + d] : 0.f;
        }
        __syncthreads();
        #pragma unroll
        for (int i = 0; i < 4; i++) {
            int r = ty + 16 * i;
            float dot = 0.f;
            #pragma unroll 16
            for (int d = 0; d < 64; d++) dot += Qs[r][d] * Ks[tx][d];
            Ps[r][tx] = (kidx[tx] >= 0) ? __expf(dot * 0.125f - slse[r]) : 0.f;
        }
        __syncthreads();
        #pragma unroll
        for (int kk = 0; kk < 16; kk++) {
            float a[4], b[4];
            #pragma unroll
            for (int i = 0; i < 4; i++) a[i] = Ps[ty + 16 * i][kk];
            #pragma unroll
            for (int j = 0; j < 4; j++) b[j] = Vs[kk][tx + 16 * j];
            #pragma unroll
            for (int i = 0; i < 4; i++)
                #pragma unroll
                for (int j = 0; j < 4; j++) acc[i][j] += a[i] * b[j];
        }
    }
    const int b = bh / NH, h = bh % NH;
    #pragma unroll
    for (int i = 0; i < 4; i++) {
        int q = q0 + ty + 16 * i;
        #pragma unroll
        for (int j = 0; j < 4; j++) {
            int d = tx + 16 * j;
            g_ctx[(b * NTOK + q) * CDIM + h * HD + d] = acc[i][j];
        }
    }
}

// ============================================================
// K7: out = ctx @ proj_w.T + proj_b (tf32 MMA)
// ============================================================
__global__ void proj_mma(const float* __restrict__ w, const float* __restrict__ bias,
                         float* __restrict__ out) {
    __shared__ unsigned As[16 * APITCH];
    __shared__ unsigned Bs[16 * BPITCH];
    float acc[2][4][4] = {};
    const int m0 = blockIdx.y * 128, n0 = blockIdx.x * 64;
    mma_tiles(g_ctx, w, CDIM, m0, n0, acc, As, Bs);

    const int tid = threadIdx.x, lane = tid & 31, wid = tid >> 5;
    const int wm = wid >> 1, wn = wid & 1, g = lane >> 2, tig = lane & 3;
    #pragma unroll
    for (int mi = 0; mi < 2; mi++)
        #pragma unroll
        for (int e2 = 0; e2 < 2; e2++) {
            int m = m0 + wm * 32 + mi * 16 + g + 8 * e2;
            #pragma unroll
            for (int nj = 0; nj < 4; nj++) {
                int n = n0 + wn * 32 + nj * 8 + tig * 2;
                *(float2*)(out + (size_t)m * CDIM + n) =
                    make_float2(acc[mi][nj][e2 * 2] + bias[n],
                                acc[mi][nj][e2 * 2 + 1] + bias[n + 1]);
            }
        }
}

// ============================================================
extern "C" void kernel_launch(void* const* d_in, const int* in_sizes, int n_in,
                              void* d_out, int out_size) {
    const float* x      = (const float*)d_in[0];
    const float* qkv_w  = (const float*)d_in[1];
    const float* proj_w = (const float*)d_in[2];
    const float* proj_b = (const float*)d_in[3];
    const int*   ce     = (const int*)d_in[4];
    float* out = (float*)d_out;

    const int qk_smem = (128 + 64) * AP * sizeof(unsigned);   // 55296 B
    static int configured = 0;
    if (!configured) {
        cudaFuncSetAttribute(qk_lse,   cudaFuncAttributeMaxDynamicSharedMemorySize, qk_smem);
        cudaFuncSetAttribute(qk_stats, cudaFuncAttributeMaxDynamicSharedMemorySize, qk_smem);
        configured = 1;
    }

    qkv_mma<<<dim3(THREEC / 64, MROWS / 128), 256>>>(x, qkv_w);
    qk_lse<<<dim3(MTILES, BH), 256, qk_smem>>>();
    qk_stats<<<dim3(MTILES, BH), 256, qk_smem>>>();
    finalize_mask<<<NTOK, 128>>>(ce);
    compact_kept<<<1, 1024>>>();
    av_sparse<<<dim3(NTOK / 64, BH), 256>>>();
    proj_mma<<<dim3(CDIM / 64, MROWS / 128), 256>>>(proj_w, proj_b, out);
}

// round 9
// speedup vs baseline: 4.1449x; 1.0139x over previous
#include <cuda_runtime.h>
#include <cuda_bf16.h>
#include <math.h>

#define BDIM   4
#define NTOK   1024
#define CDIM   768
#define NH     12
#define HD     64
#define BH     (BDIM*NH)        // 48
#define MROWS  (BDIM*NTOK)      // 4096
#define THREEC (3*CDIM)         // 2304

#define QR     64                       // q-rows per fused qk block
#define QTILES (NTOK/QR)                // 16
#define NCHUNK (BH*QTILES)              // 768 column-stat chunks

// -------- scratch (static device memory; no allocs allowed) --------
__device__ float g_q[BH*NTOK*HD];
__device__ float g_k[BH*NTOK*HD];
__device__ float g_v[BH*NTOK*HD];
__device__ float g_lse[BH*NTOK];
__device__ float g_ps[NCHUNK*NTOK];
__device__ float g_pp[NCHUNK*NTOK];
__device__ float g_mask[NTOK];
__device__ int   g_kept[NTOK];
__device__ int   g_nkept;
__device__ float g_ctx[MROWS*CDIM];

// ============================================================
// warp-MMA building blocks
// ============================================================
__device__ __forceinline__ unsigned f2tf(float f) {
    unsigned u; asm("cvt.rna.tf32.f32 %0, %1;" : "=r"(u) : "f"(f)); return u;
}
__device__ __forceinline__ void mma8(float d[4], const unsigned a[4], const unsigned b[2]) {
    asm volatile(
        "mma.sync.aligned.m16n8k8.row.col.f32.tf32.tf32.f32 "
        "{%0,%1,%2,%3}, {%4,%5,%6,%7}, {%8,%9}, {%0,%1,%2,%3};\n"
        : "+f"(d[0]), "+f"(d[1]), "+f"(d[2]), "+f"(d[3])
        : "r"(a[0]), "r"(a[1]), "r"(a[2]), "r"(a[3]), "r"(b[0]), "r"(b[1]));
}
__device__ __forceinline__ void mma16bf(float d[4], const unsigned a[4], const unsigned b[2]) {
    asm volatile(
        "mma.sync.aligned.m16n8k16.row.col.f32.bf16.bf16.f32 "
        "{%0,%1,%2,%3}, {%4,%5,%6,%7}, {%8,%9}, {%0,%1,%2,%3};\n"
        : "+f"(d[0]), "+f"(d[1]), "+f"(d[2]), "+f"(d[3])
        : "r"(a[0]), "r"(a[1]), "r"(a[2]), "r"(a[3]), "r"(b[0]), "r"(b[1]));
}
__device__ __forceinline__ unsigned pack_bf2(float lo, float hi) {
    __nv_bfloat162 h = __floats2bfloat162_rn(lo, hi);
    return *(unsigned*)&h;
}

// ------- K-chunked tf32 GEMM path (qkv / proj) -------
#define APITCH 136
#define BPITCH 72

__device__ __forceinline__ void mma_tiles(
    const float* __restrict__ A, const float* __restrict__ B,
    int K, int m0, int n0, float acc[2][4][4],
    unsigned* As, unsigned* Bs)
{
    const int tid = threadIdx.x;
    const int lane = tid & 31, wid = tid >> 5;
    const int wm = wid >> 1, wn = wid & 1;
    const int g = lane >> 2, tig = lane & 3;
    const int lr = tid >> 2;
    const int c4 = (tid & 3) * 4;

    for (int k0 = 0; k0 < K; k0 += 16) {
        __syncthreads();
        #pragma unroll
        for (int rr = 0; rr < 2; rr++) {
            const float4 v = *(const float4*)(A + (size_t)(m0 + lr + 64 * rr) * K + k0 + c4);
            As[(c4 + 0) * APITCH + lr + 64 * rr] = f2tf(v.x);
            As[(c4 + 1) * APITCH + lr + 64 * rr] = f2tf(v.y);
            As[(c4 + 2) * APITCH + lr + 64 * rr] = f2tf(v.z);
            As[(c4 + 3) * APITCH + lr + 64 * rr] = f2tf(v.w);
        }
        {
            const float4 v = *(const float4*)(B + (size_t)(n0 + lr) * K + k0 + c4);
            Bs[(c4 + 0) * BPITCH + lr] = f2tf(v.x);
            Bs[(c4 + 1) * BPITCH + lr] = f2tf(v.y);
            Bs[(c4 + 2) * BPITCH + lr] = f2tf(v.z);
            Bs[(c4 + 3) * BPITCH + lr] = f2tf(v.w);
        }
        __syncthreads();
        #pragma unroll
        for (int kk = 0; kk < 16; kk += 8) {
            unsigned a[2][4], b[4][2];
            #pragma unroll
            for (int mi = 0; mi < 2; mi++) {
                int row = wm * 32 + mi * 16 + g;
                a[mi][0] = As[(kk + tig) * APITCH + row];
                a[mi][1] = As[(kk + tig) * APITCH + row + 8];
                a[mi][2] = As[(kk + tig + 4) * APITCH + row];
                a[mi][3] = As[(kk + tig + 4) * APITCH + row + 8];
            }
            #pragma unroll
            for (int nj = 0; nj < 4; nj++) {
                int col = wn * 32 + nj * 8 + g;
                b[nj][0] = Bs[(kk + tig) * BPITCH + col];
                b[nj][1] = Bs[(kk + tig + 4) * BPITCH + col];
            }
            #pragma unroll
            for (int mi = 0; mi < 2; mi++)
                #pragma unroll
                for (int nj = 0; nj < 4; nj++)
                    mma8(acc[mi][nj], a[mi], b[nj]);
        }
    }
}

// ============================================================
// K1: qkv = x @ qkv_w.T (tf32 MMA) ; scatter into g_q/g_k/g_v
// ============================================================
__global__ void qkv_mma(const float* __restrict__ x, const float* __restrict__ w) {
    __shared__ unsigned As[16 * APITCH];
    __shared__ unsigned Bs[16 * BPITCH];
    float acc[2][4][4] = {};
    const int m0 = blockIdx.y * 128, n0 = blockIdx.x * 64;
    mma_tiles(x, w, CDIM, m0, n0, acc, As, Bs);

    const int tid = threadIdx.x, lane = tid & 31, wid = tid >> 5;
    const int wm = wid >> 1, wn = wid & 1, g = lane >> 2, tig = lane & 3;
    const int b = m0 / NTOK;
    const int three = n0 / CDIM;
    const int h = (n0 % CDIM) / HD;
    float* dst = (three == 0) ? g_q : (three == 1) ? g_k : g_v;
    const size_t base = (size_t)(b * NH + h) * NTOK * HD;
    #pragma unroll
    for (int mi = 0; mi < 2; mi++)
        #pragma unroll
        for (int e2 = 0; e2 < 2; e2++) {
            int tok = (m0 % NTOK) + wm * 32 + mi * 16 + g + 8 * e2;
            #pragma unroll
            for (int nj = 0; nj < 4; nj++) {
                int d0 = wn * 32 + nj * 8 + tig * 2;
                *(float2*)(dst + base + (size_t)tok * HD + d0) =
                    make_float2(acc[mi][nj][e2 * 2], acc[mi][nj][e2 * 2 + 1]);
            }
        }
}

// ============================================================
// K2 (FUSED): QK^T bf16 MMA, K panel smem-resident.
// pass A: online softmax -> lse ; pass B: column stats.
// Block: 256 thr, 64 q-rows x 1024 cols of one bh.
// ============================================================
#define PK 36   // uint32 (bf162-pair) pitch: 32 pairs + pad; 4g+tig banks conflict-free

__global__ void qk_fused() {
    extern __shared__ unsigned sh[];
    unsigned* Ks = sh;                   // [1024][PK]
    unsigned* Qs = sh + NTOK * PK;       // [QR][PK]
    __shared__ float sm_m[QR * 2];
    __shared__ float sm_s[QR * 2];
    __shared__ float slse[QR];
    __shared__ float cs[4][64];
    __shared__ float cp[4][64];

    const int bh = blockIdx.y;
    const int q0 = blockIdx.x * QR;
    const int tid = threadIdx.x, lane = tid & 31, wid = tid >> 5;
    const int wm = wid >> 1, wn = wid & 1;          // 4 x 2 warp grid
    const int g = lane >> 2, tig = lane & 3;
    const float* qb = g_q + (size_t)bh * NTOK * HD;
    const float* kb = g_k + (size_t)bh * NTOK * HD;

    // ---- stage K panel (1024x64 bf16) and Q tile once ----
    for (int idx = tid; idx < NTOK * 16; idx += 256) {
        int row = idx >> 4, c4 = (idx & 15) << 2;
        const float4 v = *(const float4*)(kb + (size_t)row * HD + c4);
        Ks[row * PK + (c4 >> 1)]     = pack_bf2(v.x, v.y);
        Ks[row * PK + (c4 >> 1) + 1] = pack_bf2(v.z, v.w);
    }
    for (int idx = tid; idx < QR * 16; idx += 256) {
        int row = idx >> 4, c4 = (idx & 15) << 2;
        const float4 v = *(const float4*)(qb + (size_t)(q0 + row) * HD + c4);
        Qs[row * PK + (c4 >> 1)]     = pack_bf2(v.x, v.y);
        Qs[row * PK + (c4 >> 1) + 1] = pack_bf2(v.z, v.w);
    }
    __syncthreads();

    const float scale = 0.125f;
    const int arow = wm * 16 + g;       // thread's rows: arow, arow+8

    // ================= pass A: online softmax =================
    float mrun[2] = {-1e30f, -1e30f};
    float srun[2] = {0.f, 0.f};

    for (int n0 = 0; n0 < NTOK; n0 += 64) {
        float acc[4][4] = {};
        #pragma unroll
        for (int kk = 0; kk < 32; kk += 8) {        // kpairs
            unsigned a[4], b[4][2];
            a[0] = Qs[arow * PK + kk + tig];
            a[1] = Qs[(arow + 8) * PK + kk + tig];
            a[2] = Qs[arow * PK + kk + tig + 4];
            a[3] = Qs[(arow + 8) * PK + kk + tig + 4];
            #pragma unroll
            for (int nj = 0; nj < 4; nj++) {
                int col = n0 + wn * 32 + nj * 8 + g;
                b[nj][0] = Ks[col * PK + kk + tig];
                b[nj][1] = Ks[col * PK + kk + tig + 4];
            }
            #pragma unroll
            for (int nj = 0; nj < 4; nj++) mma16bf(acc[nj], a, b[nj]);
        }
        #pragma unroll
        for (int e = 0; e < 2; e++) {               // e=0 row arow, e=1 row arow+8
            float v[8];
            #pragma unroll
            for (int nj = 0; nj < 4; nj++) {
                v[nj * 2]     = acc[nj][e * 2] * scale;
                v[nj * 2 + 1] = acc[nj][e * 2 + 1] * scale;
            }
            float mt = v[0];
            #pragma unroll
            for (int j = 1; j < 8; j++) mt = fmaxf(mt, v[j]);
            mt = fmaxf(mt, __shfl_xor_sync(~0u, mt, 1));
            mt = fmaxf(mt, __shfl_xor_sync(~0u, mt, 2));
            float mo = mrun[e];
            float mn = fmaxf(mo, mt);
            float s = 0.f;
            #pragma unroll
            for (int j = 0; j < 8; j++) s += __expf(v[j] - mn);
            s += __shfl_xor_sync(~0u, s, 1);
            s += __shfl_xor_sync(~0u, s, 2);
            srun[e] = srun[e] * __expf(mo - mn) + s;
            mrun[e] = mn;
        }
    }
    if (tig == 0) {
        #pragma unroll
        for (int e = 0; e < 2; e++) {
            int row = arow + 8 * e;
            sm_m[row * 2 + wn] = mrun[e];
            sm_s[row * 2 + wn] = srun[e];
        }
    }
    __syncthreads();
    if (tid < QR) {
        float m0v = sm_m[tid * 2], m1v = sm_m[tid * 2 + 1];
        float M = fmaxf(m0v, m1v);
        float S = sm_s[tid * 2] * __expf(m0v - M) + sm_s[tid * 2 + 1] * __expf(m1v - M);
        float l = M + __logf(S);
        slse[tid] = l;
        g_lse[bh * NTOK + q0 + tid] = l;
    }
    __syncthreads();

    // ================= pass B: column stats =================
    const int chunk = bh * QTILES + blockIdx.x;
    const float l0 = slse[arow];
    const float l1 = slse[arow + 8];

    for (int n0 = 0; n0 < NTOK; n0 += 64) {
        float acc[4][4] = {};
        #pragma unroll
        for (int kk = 0; kk < 32; kk += 8) {
            unsigned a[4], b[4][2];
            a[0] = Qs[arow * PK + kk + tig];
            a[1] = Qs[(arow + 8) * PK + kk + tig];
            a[2] = Qs[arow * PK + kk + tig + 4];
            a[3] = Qs[(arow + 8) * PK + kk + tig + 4];
            #pragma unroll
            for (int nj = 0; nj < 4; nj++) {
                int col = n0 + wn * 32 + nj * 8 + g;
                b[nj][0] = Ks[col * PK + kk + tig];
                b[nj][1] = Ks[col * PK + kk + tig + 4];
            }
            #pragma unroll
            for (int nj = 0; nj < 4; nj++) mma16bf(acc[nj], a, b[nj]);
        }
        float colS[8] = {}, colP[8] = {};
        #pragma unroll
        for (int nj = 0; nj < 4; nj++)
            #pragma unroll
            for (int c = 0; c < 2; c++) {
                float lp0 = acc[nj][c] * scale - l0;
                float p0 = __expf(lp0);
                float lp1 = acc[nj][2 + c] * scale - l1;
                float p1 = __expf(lp1);
                colS[nj * 2 + c] = p0 + p1;
                colP[nj * 2 + c] = p0 * lp0 + p1 * lp1;
            }
        #pragma unroll
        for (int j = 0; j < 8; j++) {               // reduce over g (rows)
            #pragma unroll
            for (int o = 4; o < 32; o <<= 1) {
                colS[j] += __shfl_xor_sync(~0u, colS[j], o);
                colP[j] += __shfl_xor_sync(~0u, colP[j], o);
            }
        }
        if (g == 0) {
            #pragma unroll
            for (int nj = 0; nj < 4; nj++)
                #pragma unroll
                for (int c = 0; c < 2; c++) {
                    int col = wn * 32 + nj * 8 + 2 * tig + c;
                    cs[wm][col] = colS[nj * 2 + c];
                    cp[wm][col] = colP[nj * 2 + c];
                }
        }
        __syncthreads();
        if (tid < 64) {
            g_ps[chunk * NTOK + n0 + tid] = cs[0][tid] + cs[1][tid] + cs[2][tid] + cs[3][tid];
            g_pp[chunk * NTOK + n0 + tid] = cp[0][tid] + cp[1][tid] + cp[2][tid] + cp[3][tid];
        }
        __syncthreads();
    }
}

// ============================================================
// K3: merge partials -> entropy -> mask (block per column)
// ============================================================
__global__ void finalize_mask(const int* __restrict__ cur_epoch_ptr) {
    __shared__ float rs[128], rp[128];
    const int j = blockIdx.x;
    const int tid = threadIdx.x;       // 128
    float s = 0.f, pp = 0.f;
    for (int c = tid; c < NCHUNK; c += 128) {
        s  += g_ps[c * NTOK + j];
        pp += g_pp[c * NTOK + j];
    }
    rs[tid] = s; rp[tid] = pp;
    __syncthreads();
    for (int o = 64; o > 0; o >>= 1) {
        if (tid < o) { rs[tid] += rs[tid + o]; rp[tid] += rp[tid + o]; }
        __syncthreads();
    }
    if (tid == 0) {
        float S = rs[0], PP = rp[0];
        const int ce = *cur_epoch_ptr;
        float factor = 0.f;
        for (int i = 0; i < ce; i++) factor += expf(-(float)(i + 1));
        factor *= 5.0f;
        const float thr = logf((float)CDIM) - factor;
        const float ent = logf(S) - PP / S;
        g_mask[j] = (ent <= thr) ? 1.0f : 0.0f;
    }
}

// ============================================================
// K4: compact kept columns
// ============================================================
__global__ void compact_kept() {
    __shared__ int sc[NTOK];
    const int tid = threadIdx.x;
    int m = (g_mask[tid] != 0.f) ? 1 : 0;
    sc[tid] = m;
    __syncthreads();
    for (int o = 1; o < NTOK; o <<= 1) {
        int v = (tid >= o) ? sc[tid - o] : 0;
        __syncthreads();
        sc[tid] += v;
        __syncthreads();
    }
    if (m) g_kept[sc[tid] - 1] = tid;
    if (tid == NTOK - 1) g_nkept = sc[tid];
}

// ============================================================
// K5: ctx = p[:,kept] @ v[kept,:] ; scores recomputed on the fly
// ============================================================
__global__ void av_sparse() {
    __shared__ int   kidx[16];
    __shared__ float Qs2[64][68];
    __shared__ float Ks2[16][65];
    __shared__ float Vs2[16][65];
    __shared__ float Ps[64][17];
    __shared__ float slse[64];
    const int bh = blockIdx.y;
    const int q0 = blockIdx.x * 64;
    const int tid = threadIdx.x;
    const int tx = tid & 15, ty = tid >> 4;
    const float* qb = g_q + (size_t)bh * NTOK * HD;
    const float* kb = g_k + (size_t)bh * NTOK * HD;
    const float* vb = g_v + (size_t)bh * NTOK * HD;

    for (int i = tid; i < 64 * 16; i += 256) {
        int r = i >> 4, k4 = (i & 15) << 2;
        const float4 v = *(const float4*)(qb + (size_t)(q0 + r) * HD + k4);
        *(float4*)(&Qs2[r][k4]) = v;
    }
    if (tid < 64) slse[tid] = g_lse[bh * NTOK + q0 + tid];
    const int nk = g_nkept;
    float acc[4][4] = {};

    for (int t0 = 0; t0 < nk; t0 += 16) {
        __syncthreads();
        if (tid < 16) {
            int i = t0 + tid;
            kidx[tid] = (i < nk) ? g_kept[i] : -1;
        }
        __syncthreads();
        for (int i = tid; i < 16 * 64; i += 256) {
            int c = i >> 6, d = i & 63;
            int kc = kidx[c];
            Ks2[c][d] = (kc >= 0) ? kb[(size_t)kc * HD + d] : 0.f;
            Vs2[c][d] = (kc >= 0) ? vb[(size_t)kc * HD + d] : 0.f;
        }
        __syncthreads();
        #pragma unroll
        for (int i = 0; i < 4; i++) {
            int r = ty + 16 * i;
            float dot = 0.f;
            #pragma unroll 16
            for (int d = 0; d < 64; d++) dot += Qs2[r][d] * Ks2[tx][d];
            Ps[r][tx] = (kidx[tx] >= 0) ? __expf(dot * 0.125f - slse[r]) : 0.f;
        }
        __syncthreads();
        #pragma unroll
        for (int kk = 0; kk < 16; kk++) {
            float a[4], b[4];
            #pragma unroll
            for (int i = 0; i < 4; i++) a[i] = Ps[ty + 16 * i][kk];
            #pragma unroll
            for (int j = 0; j < 4; j++) b[j] = Vs2[kk][tx + 16 * j];
            #pragma unroll
            for (int i = 0; i < 4; i++)
                #pragma unroll
                for (int j = 0; j < 4; j++) acc[i][j] += a[i] * b[j];
        }
    }
    const int b = bh / NH, h = bh % NH;
    #pragma unroll
    for (int i = 0; i < 4; i++) {
        int q = q0 + ty + 16 * i;
        #pragma unroll
        for (int j = 0; j < 4; j++) {
            int d = tx + 16 * j;
            g_ctx[(b * NTOK + q) * CDIM + h * HD + d] = acc[i][j];
        }
    }
}

// ============================================================
// K6: out = ctx @ proj_w.T + proj_b (tf32 MMA)
// ============================================================
__global__ void proj_mma(const float* __restrict__ w, const float* __restrict__ bias,
                         float* __restrict__ out) {
    __shared__ unsigned As[16 * APITCH];
    __shared__ unsigned Bs[16 * BPITCH];
    float acc[2][4][4] = {};
    const int m0 = blockIdx.y * 128, n0 = blockIdx.x * 64;
    mma_tiles(g_ctx, w, CDIM, m0, n0, acc, As, Bs);

    const int tid = threadIdx.x, lane = tid & 31, wid = tid >> 5;
    const int wm = wid >> 1, wn = wid & 1, g = lane >> 2, tig = lane & 3;
    #pragma unroll
    for (int mi = 0; mi < 2; mi++)
        #pragma unroll
        for (int e2 = 0; e2 < 2; e2++) {
            int m = m0 + wm * 32 + mi * 16 + g + 8 * e2;
            #pragma unroll
            for (int nj = 0; nj < 4; nj++) {
                int n = n0 + wn * 32 + nj * 8 + tig * 2;
                *(float2*)(out + (size_t)m * CDIM + n) =
                    make_float2(acc[mi][nj][e2 * 2] + bias[n],
                                acc[mi][nj][e2 * 2 + 1] + bias[n + 1]);
            }
        }
}

// ============================================================
extern "C" void kernel_launch(void* const* d_in, const int* in_sizes, int n_in,
                              void* d_out, int out_size) {
    const float* x      = (const float*)d_in[0];
    const float* qkv_w  = (const float*)d_in[1];
    const float* proj_w = (const float*)d_in[2];
    const float* proj_b = (const float*)d_in[3];
    const int*   ce     = (const int*)d_in[4];
    float* out = (float*)d_out;

    const int qk_smem = (NTOK + QR) * PK * sizeof(unsigned);   // 156672 B
    cudaFuncSetAttribute(qk_fused, cudaFuncAttributeMaxDynamicSharedMemorySize, qk_smem);

    qkv_mma<<<dim3(THREEC / 64, MROWS / 128), 256>>>(x, qkv_w);
    qk_fused<<<dim3(QTILES, BH), 256, qk_smem>>>();
    finalize_mask<<<NTOK, 128>>>(ce);
    compact_kept<<<1, 1024>>>();
    av_sparse<<<dim3(NTOK / 64, BH), 256>>>();
    proj_mma<<<dim3(CDIM / 64, MROWS / 128), 256>>>(proj_w, proj_b, out);
}

// round 10
// speedup vs baseline: 6.7383x; 1.6257x over previous
#include <cuda_runtime.h>
#include <cuda_bf16.h>
#include <math.h>

#define BDIM   4
#define NTOK   1024
#define CDIM   768
#define NH     12
#define HD     64
#define BH     (BDIM*NH)        // 48
#define MROWS  (BDIM*NTOK)      // 4096
#define THREEC (3*CDIM)         // 2304

#define QR     64                       // q-rows per fused qk block
#define QTILES (NTOK/QR)                // 16
#define NCHUNK (BH*QTILES)              // 768 column-stat chunks

// -------- scratch (static device memory; no allocs allowed) --------
__device__ float g_q[BH*NTOK*HD];
__device__ float g_k[BH*NTOK*HD];
__device__ float g_v[BH*NTOK*HD];
__device__ float g_lse[BH*NTOK];
__device__ float g_ps[NCHUNK*NTOK];
__device__ float g_pp[NCHUNK*NTOK];
__device__ float g_mask[NTOK];
__device__ int   g_kept[NTOK];
__device__ int   g_nkept;
__device__ float g_ctx[MROWS*CDIM];

// ============================================================
// warp-MMA building blocks
// ============================================================
__device__ __forceinline__ unsigned f2tf(float f) {
    unsigned u; asm("cvt.rna.tf32.f32 %0, %1;" : "=r"(u) : "f"(f)); return u;
}
__device__ __forceinline__ void mma8(float d[4], const unsigned a[4], const unsigned b[2]) {
    asm volatile(
        "mma.sync.aligned.m16n8k8.row.col.f32.tf32.tf32.f32 "
        "{%0,%1,%2,%3}, {%4,%5,%6,%7}, {%8,%9}, {%0,%1,%2,%3};\n"
        : "+f"(d[0]), "+f"(d[1]), "+f"(d[2]), "+f"(d[3])
        : "r"(a[0]), "r"(a[1]), "r"(a[2]), "r"(a[3]), "r"(b[0]), "r"(b[1]));
}
__device__ __forceinline__ void mma16bf(float d[4], const unsigned a[4], const unsigned b[2]) {
    asm volatile(
        "mma.sync.aligned.m16n8k16.row.col.f32.bf16.bf16.f32 "
        "{%0,%1,%2,%3}, {%4,%5,%6,%7}, {%8,%9}, {%0,%1,%2,%3};\n"
        : "+f"(d[0]), "+f"(d[1]), "+f"(d[2]), "+f"(d[3])
        : "r"(a[0]), "r"(a[1]), "r"(a[2]), "r"(a[3]), "r"(b[0]), "r"(b[1]));
}
__device__ __forceinline__ unsigned pack_bf2(float lo, float hi) {
    __nv_bfloat162 h = __floats2bfloat162_rn(lo, hi);
    return *(unsigned*)&h;
}

// ============================================================
// K1: q,k = x @ qkv_w[0:2C].T  (bf16 MMA, m16n8k16)
// C tile 128x64, 8 warps (4x2). Staging: bf16x2 pairs, pitch 20.
// ============================================================
#define PQ 20

__global__ void qkv_qk_bf16(const float* __restrict__ x, const float* __restrict__ w) {
    __shared__ unsigned As[128 * PQ];
    __shared__ unsigned Bs[64 * PQ];
    const int m0 = blockIdx.y * 128, n0 = blockIdx.x * 64;
    const int tid = threadIdx.x, lane = tid & 31, wid = tid >> 5;
    const int wm = wid >> 1, wn = wid & 1, g = lane >> 2, tig = lane & 3;
    float acc[2][4][4] = {};

    for (int k0 = 0; k0 < CDIM; k0 += 32) {
        __syncthreads();
        for (int i = tid; i < 128 * 8; i += 256) {
            int row = i >> 3, q4 = i & 7;
            const float4 v = *(const float4*)(x + (size_t)(m0 + row) * CDIM + k0 + q4 * 4);
            As[row * PQ + q4 * 2]     = pack_bf2(v.x, v.y);
            As[row * PQ + q4 * 2 + 1] = pack_bf2(v.z, v.w);
        }
        for (int i = tid; i < 64 * 8; i += 256) {
            int row = i >> 3, q4 = i & 7;
            const float4 v = *(const float4*)(w + (size_t)(n0 + row) * CDIM + k0 + q4 * 4);
            Bs[row * PQ + q4 * 2]     = pack_bf2(v.x, v.y);
            Bs[row * PQ + q4 * 2 + 1] = pack_bf2(v.z, v.w);
        }
        __syncthreads();
        #pragma unroll
        for (int kk = 0; kk < 16; kk += 8) {
            unsigned a[2][4], bfr[4][2];
            #pragma unroll
            for (int mi = 0; mi < 2; mi++) {
                int row = wm * 32 + mi * 16 + g;
                a[mi][0] = As[row * PQ + kk + tig];
                a[mi][1] = As[(row + 8) * PQ + kk + tig];
                a[mi][2] = As[row * PQ + kk + tig + 4];
                a[mi][3] = As[(row + 8) * PQ + kk + tig + 4];
            }
            #pragma unroll
            for (int nj = 0; nj < 4; nj++) {
                int col = wn * 32 + nj * 8 + g;
                bfr[nj][0] = Bs[col * PQ + kk + tig];
                bfr[nj][1] = Bs[col * PQ + kk + tig + 4];
            }
            #pragma unroll
            for (int mi = 0; mi < 2; mi++)
                #pragma unroll
                for (int nj = 0; nj < 4; nj++)
                    mma16bf(acc[mi][nj], a[mi], bfr[nj]);
        }
    }
    const int b = m0 / NTOK;
    const int three = n0 / CDIM;                 // 0 = q, 1 = k
    const int h = (n0 % CDIM) / HD;
    float* dst = (three == 0) ? g_q : g_k;
    const size_t base = (size_t)(b * NH + h) * NTOK * HD;
    #pragma unroll
    for (int mi = 0; mi < 2; mi++)
        #pragma unroll
        for (int e2 = 0; e2 < 2; e2++) {
            int tok = (m0 % NTOK) + wm * 32 + mi * 16 + g + 8 * e2;
            #pragma unroll
            for (int nj = 0; nj < 4; nj++) {
                int d0 = wn * 32 + nj * 8 + tig * 2;
                *(float2*)(dst + base + (size_t)tok * HD + d0) =
                    make_float2(acc[mi][nj][e2 * 2], acc[mi][nj][e2 * 2 + 1]);
            }
        }
}

// ============================================================
// K2 (FUSED): QK^T bf16 MMA, K panel smem-resident.
// pass A: online softmax -> lse ; pass B: column stats.
// ============================================================
#define PK 36

__global__ void qk_fused() {
    extern __shared__ unsigned sh[];
    unsigned* Ks = sh;                   // [1024][PK]
    unsigned* Qs = sh + NTOK * PK;       // [QR][PK]
    __shared__ float sm_m[QR * 2];
    __shared__ float sm_s[QR * 2];
    __shared__ float slse[QR];
    __shared__ float cs[4][64];
    __shared__ float cp[4][64];

    const int bh = blockIdx.y;
    const int q0 = blockIdx.x * QR;
    const int tid = threadIdx.x, lane = tid & 31, wid = tid >> 5;
    const int wm = wid >> 1, wn = wid & 1;
    const int g = lane >> 2, tig = lane & 3;
    const float* qb = g_q + (size_t)bh * NTOK * HD;
    const float* kb = g_k + (size_t)bh * NTOK * HD;

    for (int idx = tid; idx < NTOK * 16; idx += 256) {
        int row = idx >> 4, c4 = (idx & 15) << 2;
        const float4 v = *(const float4*)(kb + (size_t)row * HD + c4);
        Ks[row * PK + (c4 >> 1)]     = pack_bf2(v.x, v.y);
        Ks[row * PK + (c4 >> 1) + 1] = pack_bf2(v.z, v.w);
    }
    for (int idx = tid; idx < QR * 16; idx += 256) {
        int row = idx >> 4, c4 = (idx & 15) << 2;
        const float4 v = *(const float4*)(qb + (size_t)(q0 + row) * HD + c4);
        Qs[row * PK + (c4 >> 1)]     = pack_bf2(v.x, v.y);
        Qs[row * PK + (c4 >> 1) + 1] = pack_bf2(v.z, v.w);
    }
    __syncthreads();

    const float scale = 0.125f;
    const int arow = wm * 16 + g;

    // ---- pass A: online softmax ----
    float mrun[2] = {-1e30f, -1e30f};
    float srun[2] = {0.f, 0.f};

    for (int n0 = 0; n0 < NTOK; n0 += 64) {
        float acc[4][4] = {};
        #pragma unroll
        for (int kk = 0; kk < 32; kk += 8) {
            unsigned a[4], b[4][2];
            a[0] = Qs[arow * PK + kk + tig];
            a[1] = Qs[(arow + 8) * PK + kk + tig];
            a[2] = Qs[arow * PK + kk + tig + 4];
            a[3] = Qs[(arow + 8) * PK + kk + tig + 4];
            #pragma unroll
            for (int nj = 0; nj < 4; nj++) {
                int col = n0 + wn * 32 + nj * 8 + g;
                b[nj][0] = Ks[col * PK + kk + tig];
                b[nj][1] = Ks[col * PK + kk + tig + 4];
            }
            #pragma unroll
            for (int nj = 0; nj < 4; nj++) mma16bf(acc[nj], a, b[nj]);
        }
        #pragma unroll
        for (int e = 0; e < 2; e++) {
            float v[8];
            #pragma unroll
            for (int nj = 0; nj < 4; nj++) {
                v[nj * 2]     = acc[nj][e * 2] * scale;
                v[nj * 2 + 1] = acc[nj][e * 2 + 1] * scale;
            }
            float mt = v[0];
            #pragma unroll
            for (int j = 1; j < 8; j++) mt = fmaxf(mt, v[j]);
            mt = fmaxf(mt, __shfl_xor_sync(~0u, mt, 1));
            mt = fmaxf(mt, __shfl_xor_sync(~0u, mt, 2));
            float mo = mrun[e];
            float mn = fmaxf(mo, mt);
            float s = 0.f;
            #pragma unroll
            for (int j = 0; j < 8; j++) s += __expf(v[j] - mn);
            s += __shfl_xor_sync(~0u, s, 1);
            s += __shfl_xor_sync(~0u, s, 2);
            srun[e] = srun[e] * __expf(mo - mn) + s;
            mrun[e] = mn;
        }
    }
    if (tig == 0) {
        #pragma unroll
        for (int e = 0; e < 2; e++) {
            int row = arow + 8 * e;
            sm_m[row * 2 + wn] = mrun[e];
            sm_s[row * 2 + wn] = srun[e];
        }
    }
    __syncthreads();
    if (tid < QR) {
        float m0v = sm_m[tid * 2], m1v = sm_m[tid * 2 + 1];
        float M = fmaxf(m0v, m1v);
        float S = sm_s[tid * 2] * __expf(m0v - M) + sm_s[tid * 2 + 1] * __expf(m1v - M);
        float l = M + __logf(S);
        slse[tid] = l;
        g_lse[bh * NTOK + q0 + tid] = l;
    }
    __syncthreads();

    // ---- pass B: column stats ----
    const int chunk = bh * QTILES + blockIdx.x;
    const float l0 = slse[arow];
    const float l1 = slse[arow + 8];

    for (int n0 = 0; n0 < NTOK; n0 += 64) {
        float acc[4][4] = {};
        #pragma unroll
        for (int kk = 0; kk < 32; kk += 8) {
            unsigned a[4], b[4][2];
            a[0] = Qs[arow * PK + kk + tig];
            a[1] = Qs[(arow + 8) * PK + kk + tig];
            a[2] = Qs[arow * PK + kk + tig + 4];
            a[3] = Qs[(arow + 8) * PK + kk + tig + 4];
            #pragma unroll
            for (int nj = 0; nj < 4; nj++) {
                int col = n0 + wn * 32 + nj * 8 + g;
                b[nj][0] = Ks[col * PK + kk + tig];
                b[nj][1] = Ks[col * PK + kk + tig + 4];
            }
            #pragma unroll
            for (int nj = 0; nj < 4; nj++) mma16bf(acc[nj], a, b[nj]);
        }
        float colS[8] = {}, colP[8] = {};
        #pragma unroll
        for (int nj = 0; nj < 4; nj++)
            #pragma unroll
            for (int c = 0; c < 2; c++) {
                float lp0 = acc[nj][c] * scale - l0;
                float p0 = __expf(lp0);
                float lp1 = acc[nj][2 + c] * scale - l1;
                float p1 = __expf(lp1);
                colS[nj * 2 + c] = p0 + p1;
                colP[nj * 2 + c] = p0 * lp0 + p1 * lp1;
            }
        #pragma unroll
        for (int j = 0; j < 8; j++) {
            #pragma unroll
            for (int o = 4; o < 32; o <<= 1) {
                colS[j] += __shfl_xor_sync(~0u, colS[j], o);
                colP[j] += __shfl_xor_sync(~0u, colP[j], o);
            }
        }
        if (g == 0) {
            #pragma unroll
            for (int nj = 0; nj < 4; nj++)
                #pragma unroll
                for (int c = 0; c < 2; c++) {
                    int col = wn * 32 + nj * 8 + 2 * tig + c;
                    cs[wm][col] = colS[nj * 2 + c];
                    cp[wm][col] = colP[nj * 2 + c];
                }
        }
        __syncthreads();
        if (tid < 64) {
            g_ps[chunk * NTOK + n0 + tid] = cs[0][tid] + cs[1][tid] + cs[2][tid] + cs[3][tid];
            g_pp[chunk * NTOK + n0 + tid] = cp[0][tid] + cp[1][tid] + cp[2][tid] + cp[3][tid];
        }
        __syncthreads();
    }
}

// ============================================================
// K3: merge partials -> entropy -> mask (block per column)
// ============================================================
__global__ void finalize_mask(const int* __restrict__ cur_epoch_ptr) {
    __shared__ float rs[128], rp[128];
    const int j = blockIdx.x;
    const int tid = threadIdx.x;       // 128
    float s = 0.f, pp = 0.f;
    for (int c = tid; c < NCHUNK; c += 128) {
        s  += g_ps[c * NTOK + j];
        pp += g_pp[c * NTOK + j];
    }
    rs[tid] = s; rp[tid] = pp;
    __syncthreads();
    for (int o = 64; o > 0; o >>= 1) {
        if (tid < o) { rs[tid] += rs[tid + o]; rp[tid] += rp[tid + o]; }
        __syncthreads();
    }
    if (tid == 0) {
        float S = rs[0], PP = rp[0];
        const int ce = *cur_epoch_ptr;
        float factor = 0.f;
        for (int i = 0; i < ce; i++) factor += expf(-(float)(i + 1));
        factor *= 5.0f;
        const float thr = logf((float)CDIM) - factor;
        const float ent = logf(S) - PP / S;
        g_mask[j] = (ent <= thr) ? 1.0f : 0.0f;
    }
}

// ============================================================
// K4: compact kept columns
// ============================================================
__global__ void compact_kept() {
    __shared__ int sc[NTOK];
    const int tid = threadIdx.x;
    int m = (g_mask[tid] != 0.f) ? 1 : 0;
    sc[tid] = m;
    __syncthreads();
    for (int o = 1; o < NTOK; o <<= 1) {
        int v = (tid >= o) ? sc[tid - o] : 0;
        __syncthreads();
        sc[tid] += v;
        __syncthreads();
    }
    if (m) g_kept[sc[tid] - 1] = tid;
    if (tid == NTOK - 1) g_nkept = sc[tid];
}

// ============================================================
// K5: v rows for KEPT tokens only: v[bh,kc,:] = x[b,kc,:] @ Wv_h.T
// Early-exits when this block's slot range is beyond nk.
// ============================================================
__global__ void v_kept_gemm(const float* __restrict__ x, const float* __restrict__ w) {
    const int nk = g_nkept;
    const int s0 = blockIdx.x * 64;
    if (s0 >= nk) return;
    __shared__ float Xs[16][65];
    __shared__ float Ws[16][65];
    __shared__ int   toks[64];
    const int bh = blockIdx.y;
    const int b = bh / NH, h = bh % NH;
    const int tid = threadIdx.x;
    const int tx = tid & 15, ty = tid >> 4;

    if (tid < 64) {
        int s = s0 + tid;
        toks[tid] = (s < nk) ? g_kept[s] : -1;
    }
    __syncthreads();

    float acc[4][4] = {};
    for (int k0 = 0; k0 < CDIM; k0 += 16) {
        for (int idx = tid; idx < 64 * 16; idx += 256) {
            int r = idx >> 4, c = idx & 15;
            int kc = toks[r];
            Xs[c][r] = (kc >= 0) ? x[(size_t)(b * NTOK + kc) * CDIM + k0 + c] : 0.f;
            Ws[c][r] = w[(size_t)(2 * CDIM + h * HD + r) * CDIM + k0 + c];
        }
        __syncthreads();
        #pragma unroll
        for (int kk = 0; kk < 16; kk++) {
            float a[4], bb[4];
            #pragma unroll
            for (int i = 0; i < 4; i++) a[i] = Xs[kk][ty + 16 * i];
            #pragma unroll
            for (int j = 0; j < 4; j++) bb[j] = Ws[kk][tx + 16 * j];
            #pragma unroll
            for (int i = 0; i < 4; i++)
                #pragma unroll
                for (int j = 0; j < 4; j++) acc[i][j] += a[i] * bb[j];
        }
        __syncthreads();
    }
    #pragma unroll
    for (int i = 0; i < 4; i++) {
        int kc = toks[ty + 16 * i];
        if (kc >= 0) {
            #pragma unroll
            for (int j = 0; j < 4; j++)
                g_v[((size_t)bh * NTOK + kc) * HD + tx + 16 * j] = acc[i][j];
        }
    }
}

// ============================================================
// K6: ctx = p[:,kept] @ v[kept,:] ; early-exit when nk == 0
// ============================================================
__global__ void av_sparse() {
    const int nk = g_nkept;
    if (nk == 0) return;                // proj takes the bias fast path
    __shared__ int   kidx[16];
    __shared__ float Qs2[64][68];
    __shared__ float Ks2[16][65];
    __shared__ float Vs2[16][65];
    __shared__ float Ps[64][17];
    __shared__ float slse[64];
    const int bh = blockIdx.y;
    const int q0 = blockIdx.x * 64;
    const int tid = threadIdx.x;
    const int tx = tid & 15, ty = tid >> 4;
    const float* qb = g_q + (size_t)bh * NTOK * HD;
    const float* kb = g_k + (size_t)bh * NTOK * HD;
    const float* vb = g_v + (size_t)bh * NTOK * HD;

    for (int i = tid; i < 64 * 16; i += 256) {
        int r = i >> 4, k4 = (i & 15) << 2;
        const float4 v = *(const float4*)(qb + (size_t)(q0 + r) * HD + k4);
        *(float4*)(&Qs2[r][k4]) = v;
    }
    if (tid < 64) slse[tid] = g_lse[bh * NTOK + q0 + tid];
    float acc[4][4] = {};

    for (int t0 = 0; t0 < nk; t0 += 16) {
        __syncthreads();
        if (tid < 16) {
            int i = t0 + tid;
            kidx[tid] = (i < nk) ? g_kept[i] : -1;
        }
        __syncthreads();
        for (int i = tid; i < 16 * 64; i += 256) {
            int c = i >> 6, d = i & 63;
            int kc = kidx[c];
            Ks2[c][d] = (kc >= 0) ? kb[(size_t)kc * HD + d] : 0.f;
            Vs2[c][d] = (kc >= 0) ? vb[(size_t)kc * HD + d] : 0.f;
        }
        __syncthreads();
        #pragma unroll
        for (int i = 0; i < 4; i++) {
            int r = ty + 16 * i;
            float dot = 0.f;
            #pragma unroll 16
            for (int d = 0; d < 64; d++) dot += Qs2[r][d] * Ks2[tx][d];
            Ps[r][tx] = (kidx[tx] >= 0) ? __expf(dot * 0.125f - slse[r]) : 0.f;
        }
        __syncthreads();
        #pragma unroll
        for (int kk = 0; kk < 16; kk++) {
            float a[4], b[4];
            #pragma unroll
            for (int i = 0; i < 4; i++) a[i] = Ps[ty + 16 * i][kk];
            #pragma unroll
            for (int j = 0; j < 4; j++) b[j] = Vs2[kk][tx + 16 * j];
            #pragma unroll
            for (int i = 0; i < 4; i++)
                #pragma unroll
                for (int j = 0; j < 4; j++) acc[i][j] += a[i] * b[j];
        }
    }
    const int b = bh / NH, h = bh % NH;
    #pragma unroll
    for (int i = 0; i < 4; i++) {
        int q = q0 + ty + 16 * i;
        #pragma unroll
        for (int j = 0; j < 4; j++) {
            int d = tx + 16 * j;
            g_ctx[(b * NTOK + q) * CDIM + h * HD + d] = acc[i][j];
        }
    }
}

// ============================================================
// K7: out = ctx @ proj_w.T + proj_b (tf32 MMA);
// fast path when nk == 0: out rows = bias (ctx == 0).
// ============================================================
#define APITCH 136
#define BPITCH 72

__global__ void proj_mma(const float* __restrict__ w, const float* __restrict__ bias,
                         float* __restrict__ out) {
    const int m0 = blockIdx.y * 128, n0 = blockIdx.x * 64;
    const int tid = threadIdx.x;

    if (g_nkept == 0) {                 // ctx == 0 exactly -> out = bias
        float4 bv[4];
        #pragma unroll
        for (int j = 0; j < 4; j++) bv[j] = *(const float4*)(bias + n0 + (tid & 3) * 4 + 16 * j);
        for (int r = tid >> 2; r < 128; r += 64) {
            float* o = out + (size_t)(m0 + r) * CDIM + n0 + (tid & 3) * 4;
            #pragma unroll
            for (int j = 0; j < 4; j++) *(float4*)(o + 16 * j) = bv[j];
        }
        return;
    }

    __shared__ unsigned As[16 * APITCH];
    __shared__ unsigned Bs[16 * BPITCH];
    const int lane = tid & 31, wid = tid >> 5;
    const int wm = wid >> 1, wn = wid & 1;
    const int g = lane >> 2, tig = lane & 3;
    const int lr = tid >> 2;
    const int c4 = (tid & 3) * 4;
    float acc[2][4][4] = {};

    for (int k0 = 0; k0 < CDIM; k0 += 16) {
        __syncthreads();
        #pragma unroll
        for (int rr = 0; rr < 2; rr++) {
            const float4 v = *(const float4*)(g_ctx + (size_t)(m0 + lr + 64 * rr) * CDIM + k0 + c4);
            As[(c4 + 0) * APITCH + lr + 64 * rr] = f2tf(v.x);
            As[(c4 + 1) * APITCH + lr + 64 * rr] = f2tf(v.y);
            As[(c4 + 2) * APITCH + lr + 64 * rr] = f2tf(v.z);
            As[(c4 + 3) * APITCH + lr + 64 * rr] = f2tf(v.w);
        }
        {
            const float4 v = *(const float4*)(w + (size_t)(n0 + lr) * CDIM + k0 + c4);
            Bs[(c4 + 0) * BPITCH + lr] = f2tf(v.x);
            Bs[(c4 + 1) * BPITCH + lr] = f2tf(v.y);
            Bs[(c4 + 2) * BPITCH + lr] = f2tf(v.z);
            Bs[(c4 + 3) * BPITCH + lr] = f2tf(v.w);
        }
        __syncthreads();
        #pragma unroll
        for (int kk = 0; kk < 16; kk += 8) {
            unsigned a[2][4], b[4][2];
            #pragma unroll
            for (int mi = 0; mi < 2; mi++) {
                int row = wm * 32 + mi * 16 + g;
                a[mi][0] = As[(kk + tig) * APITCH + row];
                a[mi][1] = As[(kk + tig) * APITCH + row + 8];
                a[mi][2] = As[(kk + tig + 4) * APITCH + row];
                a[mi][3] = As[(kk + tig + 4) * APITCH + row + 8];
            }
            #pragma unroll
            for (int nj = 0; nj < 4; nj++) {
                int col = wn * 32 + nj * 8 + g;
                b[nj][0] = Bs[(kk + tig) * BPITCH + col];
                b[nj][1] = Bs[(kk + tig + 4) * BPITCH + col];
            }
            #pragma unroll
            for (int mi = 0; mi < 2; mi++)
                #pragma unroll
                for (int nj = 0; nj < 4; nj++)
                    mma8(acc[mi][nj], a[mi], b[nj]);
        }
    }
    #pragma unroll
    for (int mi = 0; mi < 2; mi++)
        #pragma unroll
        for (int e2 = 0; e2 < 2; e2++) {
            int m = m0 + wm * 32 + mi * 16 + g + 8 * e2;
            #pragma unroll
            for (int nj = 0; nj < 4; nj++) {
                int n = n0 + wn * 32 + nj * 8 + tig * 2;
                *(float2*)(out + (size_t)m * CDIM + n) =
                    make_float2(acc[mi][nj][e2 * 2] + bias[n],
                                acc[mi][nj][e2 * 2 + 1] + bias[n + 1]);
            }
        }
}

// ============================================================
extern "C" void kernel_launch(void* const* d_in, const int* in_sizes, int n_in,
                              void* d_out, int out_size) {
    const float* x      = (const float*)d_in[0];
    const float* qkv_w  = (const float*)d_in[1];
    const float* proj_w = (const float*)d_in[2];
    const float* proj_b = (const float*)d_in[3];
    const int*   ce     = (const int*)d_in[4];
    float* out = (float*)d_out;

    const int qk_smem = (NTOK + QR) * PK * sizeof(unsigned);   // 156672 B
    cudaFuncSetAttribute(qk_fused, cudaFuncAttributeMaxDynamicSharedMemorySize, qk_smem);

    qkv_qk_bf16<<<dim3(2 * CDIM / 64, MROWS / 128), 256>>>(x, qkv_w);
    qk_fused<<<dim3(QTILES, BH), 256, qk_smem>>>();
    finalize_mask<<<NTOK, 128>>>(ce);
    compact_kept<<<1, 1024>>>();
    v_kept_gemm<<<dim3(NTOK / 64, BH), 256>>>(x, qkv_w);
    av_sparse<<<dim3(NTOK / 64, BH), 256>>>();
    proj_mma<<<dim3(CDIM / 64, MROWS / 128), 256>>>(proj_w, proj_b, out);
}